// round 8
// baseline (speedup 1.0000x reference)
#include <cuda_runtime.h>
#include <cuda_bf16.h>
#include <cstdint>

// ============================================================================
// LinearAttentionLayer B=16,N=8192,F=128,U=128 fp32.
// mma.sync.m16n8k16 bf16 + ldmatrix, 2-term bf16 split (hh+hl+lh) ~6e-6.
// Round 8: 512-thread CTAs (4 warps/SMSP, was 2) — latency-bound fix.
// Work split: A-proj K warps 0-7 / V warps 8-15 (32x32 tiles); kv 16x64;
// B proj/out 16x32. Same smem, same per-SM MMA/LDSM totals, 2x concurrency.
// ============================================================================

namespace {
constexpr int Bb = 16, Nn = 8192;
constexpr int SUBT = 64;
constexpr int TASKS = Bb * (Nn / SUBT);   // 2048
constexpr int GRID  = 148;
constexpr int NTHR  = 512;

constexpr int SA_WKH = 0, SA_WKL = 32768, SA_WVH = 65536, SA_WVL = 98304;
constexpr int SA_XH = 131072, SA_XL = 147456;
constexpr int SA_KH = 163840, SA_KL = 180224, SA_VH = 196608, SA_VL = 212992;
constexpr int SA_BK = 229376, SA_BV = 229888;
constexpr int SA_SMEM = 230400;

constexpr int SB_WQH = 0, SB_WQL = 32768, SB_KVH = 65536, SB_KVL = 98304;
constexpr int SB_XH = 131072, SB_XL = 147456, SB_QH = 163840, SB_QL = 180224;
constexpr int SB_BQ = 196608;
constexpr int SB_SMEM = 197120;
}

__device__ float g_kv[Bb * 128 * 128];

// ---------------------------------------------------------------------------
__device__ __forceinline__ uint32_t smem_u32(const void* p) {
    uint32_t a;
    asm("{ .reg .u64 t; cvta.to.shared.u64 t, %1; cvt.u32.u64 %0, t; }" : "=r"(a) : "l"(p));
    return a;
}
__device__ __forceinline__ uint32_t swz(uint32_t row, uint32_t cb) {
    return row * 256u + (cb & 0x80u) + ((cb & 0x7Fu) ^ ((row & 7u) << 4));
}
__device__ __forceinline__ void ldsm4(uint32_t a, uint32_t* r) {
    asm volatile("ldmatrix.sync.aligned.m8n8.x4.shared.b16 {%0,%1,%2,%3}, [%4];"
        : "=r"(r[0]), "=r"(r[1]), "=r"(r[2]), "=r"(r[3]) : "r"(a));
}
__device__ __forceinline__ void ldsm4t(uint32_t a, uint32_t* r) {
    asm volatile("ldmatrix.sync.aligned.m8n8.x4.trans.shared.b16 {%0,%1,%2,%3}, [%4];"
        : "=r"(r[0]), "=r"(r[1]), "=r"(r[2]), "=r"(r[3]) : "r"(a));
}
__device__ __forceinline__ void mma16816(float* d, const uint32_t* a, const uint32_t* b) {
    asm volatile(
        "mma.sync.aligned.m16n8k16.row.col.f32.bf16.bf16.f32 "
        "{%0,%1,%2,%3}, {%4,%5,%6,%7}, {%8,%9}, {%0,%1,%2,%3};"
        : "+f"(d[0]), "+f"(d[1]), "+f"(d[2]), "+f"(d[3])
        : "r"(a[0]), "r"(a[1]), "r"(a[2]), "r"(a[3]), "r"(b[0]), "r"(b[1]));
}
__device__ __forceinline__ void mma3(float* d0, float* d1,
    const uint32_t* ah, const uint32_t* al, const uint32_t* bh, const uint32_t* bl) {
    mma16816(d0, ah, bh); mma16816(d1, ah, bh + 2);
    mma16816(d0, al, bh); mma16816(d1, al, bh + 2);
    mma16816(d0, ah, bl); mma16816(d1, ah, bl + 2);
}

__device__ __forceinline__ void split2pack(float v0, float v1, uint32_t& hp, uint32_t& lp) {
    asm("cvt.rn.bf16x2.f32 %0, %1, %2;" : "=r"(hp) : "f"(v1), "f"(v0));
    float h0 = __int_as_float(hp << 16);
    float h1 = __int_as_float(hp & 0xFFFF0000u);
    float l0 = v0 - h0, l1 = v1 - h1;
    asm("cvt.rn.bf16x2.f32 %0, %1, %2;" : "=r"(lp) : "f"(l1), "f"(l0));
}

__device__ __forceinline__ float fexp(float x) {
    float t = x * 1.4426950408889634f;
    float r = t + 12582912.0f;
    int   e = __float_as_int(r) - 0x4B400000;
    float y = (t - (r - 12582912.0f)) * 0.6931471805599453f;
    float p = 1.38888894e-3f;
    p = fmaf(p, y, 8.33333377e-3f);
    p = fmaf(p, y, 4.16666679e-2f);
    p = fmaf(p, y, 1.66666672e-1f);
    p = fmaf(p, y, 0.5f);
    p = fmaf(p, y, 1.0f);
    p = fmaf(p, y, 1.0f);
    return __int_as_float(__float_as_int(p) + (e << 23));
}

__global__ void zero_kv_kernel() {
    int i = blockIdx.x * blockDim.x + threadIdx.x;
    reinterpret_cast<float4*>(g_kv)[i] = make_float4(0.f, 0.f, 0.f, 0.f);
}

// prefetched x regs (64x128 fp32 tile, 4 float4/thread @512thr) -> hi/lo smem
__device__ __forceinline__ void store_x_regs(
    char* smem, int XHo, int XLo, const float4* xr, int tid)
{
    #pragma unroll
    for (int ii = 0; ii < 4; ++ii) {
        int i = tid + ii * NTHR;
        uint32_t r  = (uint32_t)(i >> 5);
        uint32_t cb = (uint32_t)(i & 31) * 8;
        float4 v = xr[ii];
        uint32_t hp0, lp0, hp1, lp1;
        split2pack(v.x, v.y, hp0, lp0);
        split2pack(v.z, v.w, hp1, lp1);
        *(uint2*)(smem + XHo + swz(r, cb)) = make_uint2(hp0, hp1);
        *(uint2*)(smem + XLo + swz(r, cb)) = make_uint2(lp0, lp1);
    }
}

// ===========================================================================
// Stage A
// ===========================================================================
__global__ void __launch_bounds__(NTHR, 1) stageA(
    const float* __restrict__ x,
    const float* __restrict__ Wk, const float* __restrict__ bk,
    const float* __restrict__ Wv, const float* __restrict__ bv)
{
    extern __shared__ char smem[];
    const uint32_t sb = smem_u32(smem);
    const int tid = threadIdx.x, warp = tid >> 5, lane = tid & 31;

    const int task0 = (int)((long)blockIdx.x * TASKS / GRID);
    const int task1 = (int)((long)(blockIdx.x + 1) * TASKS / GRID);

    // W split into swizzled smem
    {
        const float2* wk2 = reinterpret_cast<const float2*>(Wk);
        const float2* wv2 = reinterpret_cast<const float2*>(Wv);
        for (int i = tid; i < 8192; i += NTHR) {
            uint32_t f  = (uint32_t)(i >> 6);
            uint32_t cb = (uint32_t)(i & 63) * 4;
            float2 a = wk2[i];
            uint32_t hp, lp;
            split2pack(a.x, a.y, hp, lp);
            *(uint32_t*)(smem + SA_WKH + swz(f, cb)) = hp;
            *(uint32_t*)(smem + SA_WKL + swz(f, cb)) = lp;
            a = wv2[i];
            split2pack(a.x, a.y, hp, lp);
            *(uint32_t*)(smem + SA_WVH + swz(f, cb)) = hp;
            *(uint32_t*)(smem + SA_WVL + swz(f, cb)) = lp;
        }
        if (tid < 128) {
            ((float*)(smem + SA_BK))[tid] = bk[tid];
            ((float*)(smem + SA_BV))[tid] = bv[tid];
        }
    }

    // proj: warps 0-7 -> K, warps 8-15 -> V; 32x32 tiles (2 rowsx4 cols of 8)
    const int wgrp = warp >> 3;                  // 0=K, 1=V
    const int wl   = warp & 7;
    const int pm0  = (wl >> 2) * 32, pc0 = (wl & 3) * 32;
    const int WHo = wgrp ? SA_WVH : SA_WKH, WLo = wgrp ? SA_WVL : SA_WKL;
    const int OHo = wgrp ? SA_VH : SA_KH,  OLo = wgrp ? SA_VL : SA_KL;

    // kv: 16u x 64w tiles
    const int u0 = (warp & 7) * 16, w0 = (warp >> 3) * 64;
    const int er = lane >> 2, ec = 2 * (lane & 3);

    float kvacc[8][4];
    #pragma unroll
    for (int nb = 0; nb < 8; ++nb)
        kvacc[nb][0] = kvacc[nb][1] = kvacc[nb][2] = kvacc[nb][3] = 0.f;

    const float* sbias = (const float*)(smem + (wgrp ? SA_BV : SA_BK));
    const float4* xall = reinterpret_cast<const float4*>(x);

    float4 xr[4];
    #pragma unroll
    for (int ii = 0; ii < 4; ++ii)
        xr[ii] = xall[(size_t)task0 * 2048 + ii * NTHR + tid];

    int bcur = task0 >> 7;
    for (int t = task0; t < task1; ++t) {
        const int b = t >> 7;
        if (b != bcur) {
            float* kvb = g_kv + (size_t)bcur * 16384;
            int ur = u0 + er;
            #pragma unroll
            for (int nb = 0; nb < 8; ++nb) {
                int col = w0 + nb * 8 + ec;
                atomicAdd(&kvb[ur * 128 + col],           kvacc[nb][0]);
                atomicAdd(&kvb[ur * 128 + col + 1],       kvacc[nb][1]);
                atomicAdd(&kvb[(ur + 8) * 128 + col],     kvacc[nb][2]);
                atomicAdd(&kvb[(ur + 8) * 128 + col + 1], kvacc[nb][3]);
                kvacc[nb][0] = kvacc[nb][1] = kvacc[nb][2] = kvacc[nb][3] = 0.f;
            }
            bcur = b;
        }

        store_x_regs(smem, SA_XH, SA_XL, xr, tid);
        if (t + 1 < task1) {
            #pragma unroll
            for (int ii = 0; ii < 4; ++ii)
                xr[ii] = xall[(size_t)(t + 1) * 2048 + ii * NTHR + tid];
        }
        __syncthreads();   // X ready; all warps past prior kv phase

        // ---- projection (K or V per warp group), 32x32 tile ----
        float pa[2][4][4];
        #pragma unroll
        for (int mb = 0; mb < 2; ++mb)
            #pragma unroll
            for (int nb = 0; nb < 4; ++nb)
                pa[mb][nb][0] = pa[mb][nb][1] = pa[mb][nb][2] = pa[mb][nb][3] = 0.f;
        {
            const uint32_t arow0 = (uint32_t)(pm0 + (lane & 15));
            const uint32_t aco   = (uint32_t)((lane >> 4) & 1) * 16;
            const uint32_t brl   = (uint32_t)(lane & 15);
            #pragma unroll
            for (int ks = 0; ks < 8; ++ks) {
                uint32_t ah[2][4], al[2][4];
                uint32_t acb = (uint32_t)ks * 32 + aco;
                ldsm4(sb + SA_XH + swz(arow0,      acb), ah[0]);
                ldsm4(sb + SA_XH + swz(arow0 + 16, acb), ah[1]);
                ldsm4(sb + SA_XL + swz(arow0,      acb), al[0]);
                ldsm4(sb + SA_XL + swz(arow0 + 16, acb), al[1]);
                #pragma unroll
                for (int ng = 0; ng < 2; ++ng) {
                    uint32_t br  = (uint32_t)ks * 16 + brl;
                    uint32_t bcb = (uint32_t)(pc0 + ng * 16) * 2 + aco;
                    uint32_t bh[4], bl[4];
                    ldsm4t(sb + WHo + swz(br, bcb), bh);
                    ldsm4t(sb + WLo + swz(br, bcb), bl);
                    mma3(pa[0][2 * ng], pa[0][2 * ng + 1], ah[0], al[0], bh, bl);
                    mma3(pa[1][2 * ng], pa[1][2 * ng + 1], ah[1], al[1], bh, bl);
                }
            }
        }
        // ---- epilogue -> hi/lo smem (K warps: exp) ----
        #pragma unroll
        for (int mb = 0; mb < 2; ++mb) {
            int r0 = pm0 + mb * 16 + er;
            #pragma unroll
            for (int nb = 0; nb < 4; ++nb) {
                int col = pc0 + nb * 8 + ec;
                float b0 = sbias[col], b1 = sbias[col + 1];
                float v00 = pa[mb][nb][0] + b0, v01 = pa[mb][nb][1] + b1;
                float v10 = pa[mb][nb][2] + b0, v11 = pa[mb][nb][3] + b1;
                if (wgrp == 0) { v00 = fexp(v00); v01 = fexp(v01); v10 = fexp(v10); v11 = fexp(v11); }
                uint32_t hp, lp;
                split2pack(v00, v01, hp, lp);
                *(uint32_t*)(smem + OHo + swz((uint32_t)r0, (uint32_t)col * 2)) = hp;
                *(uint32_t*)(smem + OLo + swz((uint32_t)r0, (uint32_t)col * 2)) = lp;
                split2pack(v10, v11, hp, lp);
                *(uint32_t*)(smem + OHo + swz((uint32_t)(r0 + 8), (uint32_t)col * 2)) = hp;
                *(uint32_t*)(smem + OLo + swz((uint32_t)(r0 + 8), (uint32_t)col * 2)) = lp;
            }
        }
        __syncthreads();   // K/V ready

        // ---- kv += k^T v, 16u x 64w tile ----
        {
            const uint32_t krl = (uint32_t)(((lane >> 4) & 1) * 8 + (lane & 7));
            const uint32_t ucb = (uint32_t)(u0 + ((lane >> 3) & 1) * 8) * 2;
            const uint32_t vco = (uint32_t)((lane >> 4) & 1) * 16;
            #pragma unroll
            for (int ks = 0; ks < 4; ++ks) {
                uint32_t kah[4], kal[4];
                uint32_t kr = (uint32_t)ks * 16 + krl;
                ldsm4t(sb + SA_KH + swz(kr, ucb), kah);
                ldsm4t(sb + SA_KL + swz(kr, ucb), kal);
                #pragma unroll
                for (int ng = 0; ng < 4; ++ng) {
                    uint32_t vr  = (uint32_t)(ks * 16 + (lane & 15));
                    uint32_t vcb = (uint32_t)(w0 + ng * 16) * 2 + vco;
                    uint32_t bh[4], bl[4];
                    ldsm4t(sb + SA_VH + swz(vr, vcb), bh);
                    ldsm4t(sb + SA_VL + swz(vr, vcb), bl);
                    mma3(kvacc[2 * ng], kvacc[2 * ng + 1], kah, kal, bh, bl);
                }
            }
        }
    }

    // final flush
    {
        float* kvb = g_kv + (size_t)bcur * 16384;
        int ur = u0 + er;
        #pragma unroll
        for (int nb = 0; nb < 8; ++nb) {
            int col = w0 + nb * 8 + ec;
            atomicAdd(&kvb[ur * 128 + col],           kvacc[nb][0]);
            atomicAdd(&kvb[ur * 128 + col + 1],       kvacc[nb][1]);
            atomicAdd(&kvb[(ur + 8) * 128 + col],     kvacc[nb][2]);
            atomicAdd(&kvb[(ur + 8) * 128 + col + 1], kvacc[nb][3]);
        }
    }
}

// ===========================================================================
// Stage B
// ===========================================================================
__global__ void __launch_bounds__(NTHR, 1) stageB(
    const float* __restrict__ x,
    const float* __restrict__ Wq, const float* __restrict__ bq,
    float* __restrict__ out)
{
    extern __shared__ char smem[];
    const uint32_t sb = smem_u32(smem);
    const int tid = threadIdx.x, warp = tid >> 5, lane = tid & 31;

    const int task0 = (int)((long)blockIdx.x * TASKS / GRID);
    const int task1 = (int)((long)(blockIdx.x + 1) * TASKS / GRID);

    {
        const float2* wq2 = reinterpret_cast<const float2*>(Wq);
        for (int i = tid; i < 8192; i += NTHR) {
            uint32_t f  = (uint32_t)(i >> 6);
            uint32_t cb = (uint32_t)(i & 63) * 4;
            float2 a = wq2[i];
            uint32_t hp, lp;
            split2pack(a.x, a.y, hp, lp);
            *(uint32_t*)(smem + SB_WQH + swz(f, cb)) = hp;
            *(uint32_t*)(smem + SB_WQL + swz(f, cb)) = lp;
        }
        if (tid < 128)
            ((float*)(smem + SB_BQ))[tid] = bq[tid];
    }

    // 16x32 tiles: 4 row groups x 4 col groups = 16 warps
    const int m0 = (warp & 3) * 16, c0 = (warp >> 2) * 32;
    const int er = lane >> 2, ec = 2 * (lane & 3);
    const float* sbq = (const float*)(smem + SB_BQ);
    const float4* xall = reinterpret_cast<const float4*>(x);

    float4 xr[4];
    #pragma unroll
    for (int ii = 0; ii < 4; ++ii)
        xr[ii] = xall[(size_t)task0 * 2048 + ii * NTHR + tid];

    int bcur = -1;
    for (int t = task0; t < task1; ++t) {
        const int b = t >> 7;

        store_x_regs(smem, SB_XH, SB_XL, xr, tid);
        if (t + 1 < task1) {
            #pragma unroll
            for (int ii = 0; ii < 4; ++ii)
                xr[ii] = xall[(size_t)(t + 1) * 2048 + ii * NTHR + tid];
        }
        __syncthreads();   // X ready; all warps past prior out phase

        if (b != bcur) {   // (re)load kv tile; visibility via next sync
            const float2* kv2 = reinterpret_cast<const float2*>(g_kv) + (size_t)b * 8192;
            for (int i = tid; i < 8192; i += NTHR) {
                uint32_t f  = (uint32_t)(i >> 6);
                uint32_t cb = (uint32_t)(i & 63) * 4;
                float2 a = kv2[i];
                uint32_t hp, lp;
                split2pack(a.x, a.y, hp, lp);
                *(uint32_t*)(smem + SB_KVH + swz(f, cb)) = hp;
                *(uint32_t*)(smem + SB_KVL + swz(f, cb)) = lp;
            }
            bcur = b;
        }

        // ---- q projection, 16x32 tile ----
        float pa[4][4];
        #pragma unroll
        for (int nb = 0; nb < 4; ++nb)
            pa[nb][0] = pa[nb][1] = pa[nb][2] = pa[nb][3] = 0.f;
        {
            const uint32_t arow = (uint32_t)(m0 + (lane & 15));
            const uint32_t aco  = (uint32_t)((lane >> 4) & 1) * 16;
            const uint32_t brl  = (uint32_t)(lane & 15);
            #pragma unroll
            for (int ks = 0; ks < 8; ++ks) {
                uint32_t ah[4], al[4];
                uint32_t acb = (uint32_t)ks * 32 + aco;
                ldsm4(sb + SB_XH + swz(arow, acb), ah);
                ldsm4(sb + SB_XL + swz(arow, acb), al);
                #pragma unroll
                for (int ng = 0; ng < 2; ++ng) {
                    uint32_t br  = (uint32_t)ks * 16 + brl;
                    uint32_t bcb = (uint32_t)(c0 + ng * 16) * 2 + aco;
                    uint32_t bh[4], bl[4];
                    ldsm4t(sb + SB_WQH + swz(br, bcb), bh);
                    ldsm4t(sb + SB_WQL + swz(br, bcb), bl);
                    mma3(pa[2 * ng], pa[2 * ng + 1], ah, al, bh, bl);
                }
            }
        }
        // ---- epilogue: q = exp(.+bq) -> hi/lo smem ----
        {
            int r0 = m0 + er;
            #pragma unroll
            for (int nb = 0; nb < 4; ++nb) {
                int col = c0 + nb * 8 + ec;
                float b0 = sbq[col], b1 = sbq[col + 1];
                uint32_t hp, lp;
                split2pack(fexp(pa[nb][0] + b0), fexp(pa[nb][1] + b1), hp, lp);
                *(uint32_t*)(smem + SB_QH + swz((uint32_t)r0, (uint32_t)col * 2)) = hp;
                *(uint32_t*)(smem + SB_QL + swz((uint32_t)r0, (uint32_t)col * 2)) = lp;
                split2pack(fexp(pa[nb][2] + b0), fexp(pa[nb][3] + b1), hp, lp);
                *(uint32_t*)(smem + SB_QH + swz((uint32_t)(r0 + 8), (uint32_t)col * 2)) = hp;
                *(uint32_t*)(smem + SB_QL + swz((uint32_t)(r0 + 8), (uint32_t)col * 2)) = lp;
            }
        }
        __syncthreads();   // Q (and any reloaded KV) ready

        // ---- out = q @ kv, 16x32 tile ----
        float oa[4][4];
        #pragma unroll
        for (int nb = 0; nb < 4; ++nb)
            oa[nb][0] = oa[nb][1] = oa[nb][2] = oa[nb][3] = 0.f;
        {
            const uint32_t arow = (uint32_t)(m0 + (lane & 15));
            const uint32_t aco  = (uint32_t)((lane >> 4) & 1) * 16;
            const uint32_t brl  = (uint32_t)(lane & 15);
            #pragma unroll
            for (int ks = 0; ks < 8; ++ks) {
                uint32_t ah[4], al[4];
                uint32_t acb = (uint32_t)ks * 32 + aco;
                ldsm4(sb + SB_QH + swz(arow, acb), ah);
                ldsm4(sb + SB_QL + swz(arow, acb), al);
                #pragma unroll
                for (int ng = 0; ng < 2; ++ng) {
                    uint32_t br  = (uint32_t)ks * 16 + brl;
                    uint32_t bcb = (uint32_t)(c0 + ng * 16) * 2 + aco;
                    uint32_t bh[4], bl[4];
                    ldsm4t(sb + SB_KVH + swz(br, bcb), bh);
                    ldsm4t(sb + SB_KVL + swz(br, bcb), bl);
                    mma3(oa[2 * ng], oa[2 * ng + 1], ah, al, bh, bl);
                }
            }
        }
        // store
        float* og = out + (size_t)t * 8192;
        {
            int r0 = m0 + er;
            #pragma unroll
            for (int nb = 0; nb < 4; ++nb) {
                int col = c0 + nb * 8 + ec;
                *(float2*)(og + (size_t)r0 * 128 + col)       = make_float2(oa[nb][0], oa[nb][1]);
                *(float2*)(og + (size_t)(r0 + 8) * 128 + col) = make_float2(oa[nb][2], oa[nb][3]);
            }
        }
    }
}

// ---------------------------------------------------------------------------
extern "C" void kernel_launch(void* const* d_in, const int* in_sizes, int n_in,
                              void* d_out, int out_size) {
    const float* x  = (const float*)d_in[0];
    const float* Wq = (const float*)d_in[1];
    const float* bq = (const float*)d_in[2];
    const float* Wk = (const float*)d_in[3];
    const float* bk = (const float*)d_in[4];
    const float* Wv = (const float*)d_in[5];
    const float* bv = (const float*)d_in[6];
    float* out = (float*)d_out;
    (void)in_sizes; (void)n_in; (void)out_size;

    cudaFuncSetAttribute(stageA, cudaFuncAttributeMaxDynamicSharedMemorySize, SA_SMEM);
    cudaFuncSetAttribute(stageB, cudaFuncAttributeMaxDynamicSharedMemorySize, SB_SMEM);

    zero_kv_kernel<<<256, 256>>>();
    stageA<<<GRID, NTHR, SA_SMEM>>>(x, Wk, bk, Wv, bv);
    stageB<<<GRID, NTHR, SB_SMEM>>>(x, Wq, bq, out);
}

// round 10
// speedup vs baseline: 1.4508x; 1.4508x over previous
#include <cuda_runtime.h>
#include <cuda_fp16.h>
#include <cstdint>

// ============================================================================
// LinearAttentionLayer B=16,N=8192,F=128,U=128 fp32.
// Round 10 (= round 9 resubmit after infra failure):
// fp16 asymmetric 2-pass split — A=(Ah+Al) fp16, B single fp16.
// C ~ AhBh + AlBh. Error ~1.1e-4/GEMM (~2e-4 chained), 2/3 the MMAs and
// ~2/3 the LDSM of the bf16 3-pass scheme. Structure = round-7 champion
// (256 thr, 32x32 proj tiles fused K/V, 32x64 kv tiles, prefetch, 148 CTAs).
// ============================================================================

namespace {
constexpr int Bb = 16, Nn = 8192;
constexpr int SUBT = 64;
constexpr int TASKS = Bb * (Nn / SUBT);   // 2048
constexpr int GRID  = 148;

// stage A smem (bytes): W hi-only; X,K hi+lo; V hi-only
constexpr int SA_WKH = 0;            // 128x128 fp16 = 32768
constexpr int SA_WVH = 32768;
constexpr int SA_XH  = 65536;        // 64x128 fp16 = 16384
constexpr int SA_XL  = 81920;
constexpr int SA_KH  = 98304;
constexpr int SA_KL  = 114688;
constexpr int SA_VH  = 131072;
constexpr int SA_BK  = 147456, SA_BV = 147968;
constexpr int SA_SMEM = 148480;

// stage B: WQ hi, KV hi, X hi/lo, Q hi/lo
constexpr int SB_WQH = 0;
constexpr int SB_KVH = 32768;
constexpr int SB_XH  = 65536;
constexpr int SB_XL  = 81920;
constexpr int SB_QH  = 98304;
constexpr int SB_QL  = 114688;
constexpr int SB_BQ  = 131072;
constexpr int SB_SMEM = 131584;
}

__device__ float g_kv[Bb * 128 * 128];

// ---------------------------------------------------------------------------
__device__ __forceinline__ uint32_t smem_u32(const void* p) {
    uint32_t a;
    asm("{ .reg .u64 t; cvta.to.shared.u64 t, %1; cvt.u32.u64 %0, t; }" : "=r"(a) : "l"(p));
    return a;
}
__device__ __forceinline__ uint32_t swz(uint32_t row, uint32_t cb) {
    return row * 256u + (cb & 0x80u) + ((cb & 0x7Fu) ^ ((row & 7u) << 4));
}
__device__ __forceinline__ void ldsm4(uint32_t a, uint32_t* r) {
    asm volatile("ldmatrix.sync.aligned.m8n8.x4.shared.b16 {%0,%1,%2,%3}, [%4];"
        : "=r"(r[0]), "=r"(r[1]), "=r"(r[2]), "=r"(r[3]) : "r"(a));
}
__device__ __forceinline__ void ldsm4t(uint32_t a, uint32_t* r) {
    asm volatile("ldmatrix.sync.aligned.m8n8.x4.trans.shared.b16 {%0,%1,%2,%3}, [%4];"
        : "=r"(r[0]), "=r"(r[1]), "=r"(r[2]), "=r"(r[3]) : "r"(a));
}
__device__ __forceinline__ void mma16816f(float* d, const uint32_t* a, const uint32_t* b) {
    asm volatile(
        "mma.sync.aligned.m16n8k16.row.col.f32.f16.f16.f32 "
        "{%0,%1,%2,%3}, {%4,%5,%6,%7}, {%8,%9}, {%0,%1,%2,%3};"
        : "+f"(d[0]), "+f"(d[1]), "+f"(d[2]), "+f"(d[3])
        : "r"(a[0]), "r"(a[1]), "r"(a[2]), "r"(a[3]), "r"(b[0]), "r"(b[1]));
}
// 2-pass split MMA into a 16x16 output: (Ah + Al) x Bh
__device__ __forceinline__ void mma2(float* d0, float* d1,
    const uint32_t* ah, const uint32_t* al, const uint32_t* bh) {
    mma16816f(d0, ah, bh); mma16816f(d1, ah, bh + 2);
    mma16816f(d0, al, bh); mma16816f(d1, al, bh + 2);
}

// fp16 hi/lo split of a pair, packed
__device__ __forceinline__ void split2pack16(float v0, float v1, uint32_t& hp, uint32_t& lp) {
    __half2 h = __floats2half2_rn(v0, v1);
    float2 hf = __half22float2(h);
    __half2 l = __floats2half2_rn(v0 - hf.x, v1 - hf.y);
    hp = *reinterpret_cast<uint32_t*>(&h);
    lp = *reinterpret_cast<uint32_t*>(&l);
}
__device__ __forceinline__ uint32_t pack16(float v0, float v1) {
    __half2 h = __floats2half2_rn(v0, v1);
    return *reinterpret_cast<uint32_t*>(&h);
}

__device__ __forceinline__ float fexp(float x) {
    float t = x * 1.4426950408889634f;
    float r = t + 12582912.0f;
    int   e = __float_as_int(r) - 0x4B400000;
    float y = (t - (r - 12582912.0f)) * 0.6931471805599453f;
    float p = 1.38888894e-3f;
    p = fmaf(p, y, 8.33333377e-3f);
    p = fmaf(p, y, 4.16666679e-2f);
    p = fmaf(p, y, 1.66666672e-1f);
    p = fmaf(p, y, 0.5f);
    p = fmaf(p, y, 1.0f);
    p = fmaf(p, y, 1.0f);
    return __int_as_float(__float_as_int(p) + (e << 23));
}

__global__ void zero_kv_kernel() {
    int i = blockIdx.x * blockDim.x + threadIdx.x;
    reinterpret_cast<float4*>(g_kv)[i] = make_float4(0.f, 0.f, 0.f, 0.f);
}

// prefetched x regs (64x128 fp32 tile) -> fp16 hi/lo swizzled smem
__device__ __forceinline__ void store_x_regs(
    char* smem, int XHo, int XLo, const float4* xr, int tid)
{
    #pragma unroll
    for (int ii = 0; ii < 8; ++ii) {
        int i = tid + ii * 256;
        uint32_t r  = (uint32_t)(i >> 5);
        uint32_t cb = (uint32_t)(i & 31) * 8;
        float4 v = xr[ii];
        uint32_t hp0, lp0, hp1, lp1;
        split2pack16(v.x, v.y, hp0, lp0);
        split2pack16(v.z, v.w, hp1, lp1);
        *(uint2*)(smem + XHo + swz(r, cb)) = make_uint2(hp0, hp1);
        *(uint2*)(smem + XLo + swz(r, cb)) = make_uint2(lp0, lp1);
    }
}

// ===========================================================================
// Stage A
// ===========================================================================
__global__ void __launch_bounds__(256, 1) stageA(
    const float* __restrict__ x,
    const float* __restrict__ Wk, const float* __restrict__ bk,
    const float* __restrict__ Wv, const float* __restrict__ bv)
{
    extern __shared__ char smem[];
    const uint32_t sb = smem_u32(smem);
    const int tid = threadIdx.x, warp = tid >> 5, lane = tid & 31;

    const int task0 = (int)((long)blockIdx.x * TASKS / GRID);
    const int task1 = (int)((long)(blockIdx.x + 1) * TASKS / GRID);

    // W (hi only) into swizzled smem
    {
        const float2* wk2 = reinterpret_cast<const float2*>(Wk);
        const float2* wv2 = reinterpret_cast<const float2*>(Wv);
        for (int i = tid; i < 8192; i += 256) {
            uint32_t f  = (uint32_t)(i >> 6);
            uint32_t cb = (uint32_t)(i & 63) * 4;
            float2 a = wk2[i];
            *(uint32_t*)(smem + SA_WKH + swz(f, cb)) = pack16(a.x, a.y);
            a = wv2[i];
            *(uint32_t*)(smem + SA_WVH + swz(f, cb)) = pack16(a.x, a.y);
        }
        if (tid < 128) {
            ((float*)(smem + SA_BK))[tid] = bk[tid];
            ((float*)(smem + SA_BV))[tid] = bv[tid];
        }
    }

    // warp coords: proj tile 32x32; kv tile 32u x 64w
    const int pm0 = (warp >> 2) * 32, pc0 = (warp & 3) * 32;
    const int u0  = (warp & 3) * 32,  w0  = (warp >> 2) * 64;
    const int er = lane >> 2, ec = 2 * (lane & 3);

    float kvacc[2][8][4];
    #pragma unroll
    for (int mb = 0; mb < 2; ++mb)
        #pragma unroll
        for (int nb = 0; nb < 8; ++nb)
            kvacc[mb][nb][0] = kvacc[mb][nb][1] = kvacc[mb][nb][2] = kvacc[mb][nb][3] = 0.f;

    const float* sbk = (const float*)(smem + SA_BK);
    const float* sbv = (const float*)(smem + SA_BV);
    const float4* xall = reinterpret_cast<const float4*>(x);

    float4 xr[8];
    #pragma unroll
    for (int ii = 0; ii < 8; ++ii)
        xr[ii] = xall[(size_t)task0 * 2048 + ii * 256 + tid];

    int bcur = task0 >> 7;
    for (int t = task0; t < task1; ++t) {
        const int b = t >> 7;
        if (b != bcur) {
            float* kvb = g_kv + (size_t)bcur * 16384;
            #pragma unroll
            for (int mb = 0; mb < 2; ++mb) {
                int ur = u0 + mb * 16 + er;
                #pragma unroll
                for (int nb = 0; nb < 8; ++nb) {
                    int col = w0 + nb * 8 + ec;
                    atomicAdd(&kvb[ur * 128 + col],           kvacc[mb][nb][0]);
                    atomicAdd(&kvb[ur * 128 + col + 1],       kvacc[mb][nb][1]);
                    atomicAdd(&kvb[(ur + 8) * 128 + col],     kvacc[mb][nb][2]);
                    atomicAdd(&kvb[(ur + 8) * 128 + col + 1], kvacc[mb][nb][3]);
                    kvacc[mb][nb][0] = kvacc[mb][nb][1] = kvacc[mb][nb][2] = kvacc[mb][nb][3] = 0.f;
                }
            }
            bcur = b;
        }

        store_x_regs(smem, SA_XH, SA_XL, xr, tid);
        if (t + 1 < task1) {
            #pragma unroll
            for (int ii = 0; ii < 8; ++ii)
                xr[ii] = xall[(size_t)(t + 1) * 2048 + ii * 256 + tid];
        }
        __syncthreads();   // X ready; all warps done with prior kv phase

        // ---- fused K/V projection, warp tile 32x32, 2-pass split ----
        float ka[2][4][4], va[2][4][4];
        #pragma unroll
        for (int mb = 0; mb < 2; ++mb)
            #pragma unroll
            for (int nb = 0; nb < 4; ++nb) {
                ka[mb][nb][0] = ka[mb][nb][1] = ka[mb][nb][2] = ka[mb][nb][3] = 0.f;
                va[mb][nb][0] = va[mb][nb][1] = va[mb][nb][2] = va[mb][nb][3] = 0.f;
            }
        {
            const uint32_t arow0 = (uint32_t)(pm0 + (lane & 15));
            const uint32_t aco   = (uint32_t)((lane >> 4) & 1) * 16;
            const uint32_t brl   = (uint32_t)(lane & 15);
            #pragma unroll
            for (int ks = 0; ks < 8; ++ks) {
                uint32_t ah[2][4], al[2][4];
                uint32_t acb = (uint32_t)ks * 32 + aco;
                ldsm4(sb + SA_XH + swz(arow0,      acb), ah[0]);
                ldsm4(sb + SA_XH + swz(arow0 + 16, acb), ah[1]);
                ldsm4(sb + SA_XL + swz(arow0,      acb), al[0]);
                ldsm4(sb + SA_XL + swz(arow0 + 16, acb), al[1]);
                #pragma unroll
                for (int ng = 0; ng < 2; ++ng) {
                    uint32_t br  = (uint32_t)ks * 16 + brl;
                    uint32_t bcb = (uint32_t)(pc0 + ng * 16) * 2 + aco;
                    uint32_t bh[4];
                    ldsm4t(sb + SA_WKH + swz(br, bcb), bh);
                    mma2(ka[0][2 * ng], ka[0][2 * ng + 1], ah[0], al[0], bh);
                    mma2(ka[1][2 * ng], ka[1][2 * ng + 1], ah[1], al[1], bh);
                    ldsm4t(sb + SA_WVH + swz(br, bcb), bh);
                    mma2(va[0][2 * ng], va[0][2 * ng + 1], ah[0], al[0], bh);
                    mma2(va[1][2 * ng], va[1][2 * ng + 1], ah[1], al[1], bh);
                }
            }
        }
        // ---- epilogue: k=exp(.+bk) -> hi/lo; v=.+bv -> hi only ----
        #pragma unroll
        for (int mb = 0; mb < 2; ++mb) {
            int r0 = pm0 + mb * 16 + er;
            #pragma unroll
            for (int nb = 0; nb < 4; ++nb) {
                int col = pc0 + nb * 8 + ec;
                float bk0 = sbk[col], bk1 = sbk[col + 1];
                float bv0 = sbv[col], bv1 = sbv[col + 1];
                uint32_t hp, lp;
                split2pack16(fexp(ka[mb][nb][0] + bk0), fexp(ka[mb][nb][1] + bk1), hp, lp);
                *(uint32_t*)(smem + SA_KH + swz((uint32_t)r0, (uint32_t)col * 2)) = hp;
                *(uint32_t*)(smem + SA_KL + swz((uint32_t)r0, (uint32_t)col * 2)) = lp;
                split2pack16(fexp(ka[mb][nb][2] + bk0), fexp(ka[mb][nb][3] + bk1), hp, lp);
                *(uint32_t*)(smem + SA_KH + swz((uint32_t)(r0 + 8), (uint32_t)col * 2)) = hp;
                *(uint32_t*)(smem + SA_KL + swz((uint32_t)(r0 + 8), (uint32_t)col * 2)) = lp;
                *(uint32_t*)(smem + SA_VH + swz((uint32_t)r0, (uint32_t)col * 2)) =
                    pack16(va[mb][nb][0] + bv0, va[mb][nb][1] + bv1);
                *(uint32_t*)(smem + SA_VH + swz((uint32_t)(r0 + 8), (uint32_t)col * 2)) =
                    pack16(va[mb][nb][2] + bv0, va[mb][nb][3] + bv1);
            }
        }
        __syncthreads();   // K/V ready

        // ---- kv += k^T v, warp tile 32u x 64w ----
        {
            const uint32_t krl = (uint32_t)(((lane >> 4) & 1) * 8 + (lane & 7));
            const uint32_t vco = (uint32_t)((lane >> 4) & 1) * 16;
            #pragma unroll
            for (int ks = 0; ks < 4; ++ks) {
                uint32_t kah[2][4], kal[2][4];
                uint32_t kr = (uint32_t)ks * 16 + krl;
                #pragma unroll
                for (int mb = 0; mb < 2; ++mb) {
                    uint32_t ucb = (uint32_t)(u0 + mb * 16 + ((lane >> 3) & 1) * 8) * 2;
                    ldsm4t(sb + SA_KH + swz(kr, ucb), kah[mb]);
                    ldsm4t(sb + SA_KL + swz(kr, ucb), kal[mb]);
                }
                #pragma unroll
                for (int ng = 0; ng < 4; ++ng) {
                    uint32_t vr  = (uint32_t)(ks * 16 + (lane & 15));
                    uint32_t vcb = (uint32_t)(w0 + ng * 16) * 2 + vco;
                    uint32_t bh[4];
                    ldsm4t(sb + SA_VH + swz(vr, vcb), bh);
                    mma2(kvacc[0][2 * ng], kvacc[0][2 * ng + 1], kah[0], kal[0], bh);
                    mma2(kvacc[1][2 * ng], kvacc[1][2 * ng + 1], kah[1], kal[1], bh);
                }
            }
        }
    }

    // final flush
    {
        float* kvb = g_kv + (size_t)bcur * 16384;
        #pragma unroll
        for (int mb = 0; mb < 2; ++mb) {
            int ur = u0 + mb * 16 + er;
            #pragma unroll
            for (int nb = 0; nb < 8; ++nb) {
                int col = w0 + nb * 8 + ec;
                atomicAdd(&kvb[ur * 128 + col],           kvacc[mb][nb][0]);
                atomicAdd(&kvb[ur * 128 + col + 1],       kvacc[mb][nb][1]);
                atomicAdd(&kvb[(ur + 8) * 128 + col],     kvacc[mb][nb][2]);
                atomicAdd(&kvb[(ur + 8) * 128 + col + 1], kvacc[mb][nb][3]);
            }
        }
    }
}

// ===========================================================================
// Stage B
// ===========================================================================
__global__ void __launch_bounds__(256, 1) stageB(
    const float* __restrict__ x,
    const float* __restrict__ Wq, const float* __restrict__ bq,
    float* __restrict__ out)
{
    extern __shared__ char smem[];
    const uint32_t sb = smem_u32(smem);
    const int tid = threadIdx.x, warp = tid >> 5, lane = tid & 31;

    const int task0 = (int)((long)blockIdx.x * TASKS / GRID);
    const int task1 = (int)((long)(blockIdx.x + 1) * TASKS / GRID);

    {
        const float2* wq2 = reinterpret_cast<const float2*>(Wq);
        for (int i = tid; i < 8192; i += 256) {
            uint32_t f  = (uint32_t)(i >> 6);
            uint32_t cb = (uint32_t)(i & 63) * 4;
            float2 a = wq2[i];
            *(uint32_t*)(smem + SB_WQH + swz(f, cb)) = pack16(a.x, a.y);
        }
        if (tid < 128)
            ((float*)(smem + SB_BQ))[tid] = bq[tid];
    }

    const int m0 = (warp >> 2) * 32, c0 = (warp & 3) * 32;
    const int er = lane >> 2, ec = 2 * (lane & 3);
    const float* sbq = (const float*)(smem + SB_BQ);
    const float4* xall = reinterpret_cast<const float4*>(x);

    float4 xr[8];
    #pragma unroll
    for (int ii = 0; ii < 8; ++ii)
        xr[ii] = xall[(size_t)task0 * 2048 + ii * 256 + tid];

    int bcur = -1;
    for (int t = task0; t < task1; ++t) {
        const int b = t >> 7;

        store_x_regs(smem, SB_XH, SB_XL, xr, tid);
        if (t + 1 < task1) {
            #pragma unroll
            for (int ii = 0; ii < 8; ++ii)
                xr[ii] = xall[(size_t)(t + 1) * 2048 + ii * 256 + tid];
        }
        __syncthreads();   // X ready; all warps past prior out phase

        if (b != bcur) {   // (re)load kv tile (hi only); visibility via next sync
            const float2* kv2 = reinterpret_cast<const float2*>(g_kv) + (size_t)b * 8192;
            for (int i = tid; i < 8192; i += 256) {
                uint32_t f  = (uint32_t)(i >> 6);
                uint32_t cb = (uint32_t)(i & 63) * 4;
                float2 a = kv2[i];
                *(uint32_t*)(smem + SB_KVH + swz(f, cb)) = pack16(a.x, a.y);
            }
            bcur = b;
        }

        // ---- q projection, warp tile 32x32 ----
        float pa[2][4][4];
        #pragma unroll
        for (int mb = 0; mb < 2; ++mb)
            #pragma unroll
            for (int nb = 0; nb < 4; ++nb)
                pa[mb][nb][0] = pa[mb][nb][1] = pa[mb][nb][2] = pa[mb][nb][3] = 0.f;
        {
            const uint32_t arow0 = (uint32_t)(m0 + (lane & 15));
            const uint32_t aco   = (uint32_t)((lane >> 4) & 1) * 16;
            const uint32_t brl   = (uint32_t)(lane & 15);
            #pragma unroll
            for (int ks = 0; ks < 8; ++ks) {
                uint32_t ah[2][4], al[2][4];
                uint32_t acb = (uint32_t)ks * 32 + aco;
                ldsm4(sb + SB_XH + swz(arow0,      acb), ah[0]);
                ldsm4(sb + SB_XH + swz(arow0 + 16, acb), ah[1]);
                ldsm4(sb + SB_XL + swz(arow0,      acb), al[0]);
                ldsm4(sb + SB_XL + swz(arow0 + 16, acb), al[1]);
                #pragma unroll
                for (int ng = 0; ng < 2; ++ng) {
                    uint32_t br  = (uint32_t)ks * 16 + brl;
                    uint32_t bcb = (uint32_t)(c0 + ng * 16) * 2 + aco;
                    uint32_t bh[4];
                    ldsm4t(sb + SB_WQH + swz(br, bcb), bh);
                    mma2(pa[0][2 * ng], pa[0][2 * ng + 1], ah[0], al[0], bh);
                    mma2(pa[1][2 * ng], pa[1][2 * ng + 1], ah[1], al[1], bh);
                }
            }
        }
        // ---- epilogue: q = exp(.+bq) -> hi/lo smem ----
        #pragma unroll
        for (int mb = 0; mb < 2; ++mb) {
            int r0 = m0 + mb * 16 + er;
            #pragma unroll
            for (int nb = 0; nb < 4; ++nb) {
                int col = c0 + nb * 8 + ec;
                float b0 = sbq[col], b1 = sbq[col + 1];
                uint32_t hp, lp;
                split2pack16(fexp(pa[mb][nb][0] + b0), fexp(pa[mb][nb][1] + b1), hp, lp);
                *(uint32_t*)(smem + SB_QH + swz((uint32_t)r0, (uint32_t)col * 2)) = hp;
                *(uint32_t*)(smem + SB_QL + swz((uint32_t)r0, (uint32_t)col * 2)) = lp;
                split2pack16(fexp(pa[mb][nb][2] + b0), fexp(pa[mb][nb][3] + b1), hp, lp);
                *(uint32_t*)(smem + SB_QH + swz((uint32_t)(r0 + 8), (uint32_t)col * 2)) = hp;
                *(uint32_t*)(smem + SB_QL + swz((uint32_t)(r0 + 8), (uint32_t)col * 2)) = lp;
            }
        }
        __syncthreads();   // Q (and any reloaded KV) ready

        // ---- out = q @ kv, warp tile 32x32 ----
        float oa[2][4][4];
        #pragma unroll
        for (int mb = 0; mb < 2; ++mb)
            #pragma unroll
            for (int nb = 0; nb < 4; ++nb)
                oa[mb][nb][0] = oa[mb][nb][1] = oa[mb][nb][2] = oa[mb][nb][3] = 0.f;
        {
            const uint32_t arow0 = (uint32_t)(m0 + (lane & 15));
            const uint32_t aco   = (uint32_t)((lane >> 4) & 1) * 16;
            const uint32_t brl   = (uint32_t)(lane & 15);
            #pragma unroll
            for (int ks = 0; ks < 8; ++ks) {
                uint32_t ah[2][4], al[2][4];
                uint32_t acb = (uint32_t)ks * 32 + aco;
                ldsm4(sb + SB_QH + swz(arow0,      acb), ah[0]);
                ldsm4(sb + SB_QH + swz(arow0 + 16, acb), ah[1]);
                ldsm4(sb + SB_QL + swz(arow0,      acb), al[0]);
                ldsm4(sb + SB_QL + swz(arow0 + 16, acb), al[1]);
                #pragma unroll
                for (int ng = 0; ng < 2; ++ng) {
                    uint32_t br  = (uint32_t)ks * 16 + brl;
                    uint32_t bcb = (uint32_t)(c0 + ng * 16) * 2 + aco;
                    uint32_t bh[4];
                    ldsm4t(sb + SB_KVH + swz(br, bcb), bh);
                    mma2(oa[0][2 * ng], oa[0][2 * ng + 1], ah[0], al[0], bh);
                    mma2(oa[1][2 * ng], oa[1][2 * ng + 1], ah[1], al[1], bh);
                }
            }
        }
        // store
        float* og = out + (size_t)t * 8192;
        #pragma unroll
        for (int mb = 0; mb < 2; ++mb) {
            int r0 = m0 + mb * 16 + er;
            #pragma unroll
            for (int nb = 0; nb < 4; ++nb) {
                int col = c0 + nb * 8 + ec;
                *(float2*)(og + (size_t)r0 * 128 + col)       = make_float2(oa[mb][nb][0], oa[mb][nb][1]);
                *(float2*)(og + (size_t)(r0 + 8) * 128 + col) = make_float2(oa[mb][nb][2], oa[mb][nb][3]);
            }
        }
    }
}

// ---------------------------------------------------------------------------
extern "C" void kernel_launch(void* const* d_in, const int* in_sizes, int n_in,
                              void* d_out, int out_size) {
    const float* x  = (const float*)d_in[0];
    const float* Wq = (const float*)d_in[1];
    const float* bq = (const float*)d_in[2];
    const float* Wk = (const float*)d_in[3];
    const float* bk = (const float*)d_in[4];
    const float* Wv = (const float*)d_in[5];
    const float* bv = (const float*)d_in[6];
    float* out = (float*)d_out;
    (void)in_sizes; (void)n_in; (void)out_size;

    cudaFuncSetAttribute(stageA, cudaFuncAttributeMaxDynamicSharedMemorySize, SA_SMEM);
    cudaFuncSetAttribute(stageB, cudaFuncAttributeMaxDynamicSharedMemorySize, SB_SMEM);

    zero_kv_kernel<<<256, 256>>>();
    stageA<<<GRID, 256, SA_SMEM>>>(x, Wk, bk, Wv, bv);
    stageB<<<GRID, 256, SB_SMEM>>>(x, Wq, bq, out);
}

// round 11
// speedup vs baseline: 1.6276x; 1.1219x over previous
#include <cuda_runtime.h>
#include <cuda_fp16.h>
#include <cstdint>

// ============================================================================
// LinearAttentionLayer B=16,N=8192,F=128,U=128 fp32.
// Round 11: fp16 split, precision passes only where they matter:
//   K,Q projections: A=(xh+xl) 2-pass (k,q feed A-side hi/lo operands)
//   V projection:    A=xh single-pass (v rounded to fp16 for storage anyway)
//   kv GEMM:         A=(kh+kl) 2-pass, B=vh
//   out GEMM:        A=qh single-pass, B=kvh (kv already hi-rounded)
// Stage B: QL dropped -> 112.5KB smem -> 2 CTAs/SM (grid 296, lb(256,2)).
// ============================================================================

namespace {
constexpr int Bb = 16, Nn = 8192;
constexpr int SUBT = 64;
constexpr int TASKS = Bb * (Nn / SUBT);   // 2048
constexpr int GRIDA = 148;
constexpr int GRIDB = 296;                // 2 CTAs/SM

// stage A smem (bytes)
constexpr int SA_WKH = 0;            // 128x128 fp16 = 32768
constexpr int SA_WVH = 32768;
constexpr int SA_XH  = 65536;        // 64x128 fp16 = 16384
constexpr int SA_XL  = 81920;
constexpr int SA_KH  = 98304;
constexpr int SA_KL  = 114688;
constexpr int SA_VH  = 131072;
constexpr int SA_BK  = 147456, SA_BV = 147968;
constexpr int SA_SMEM = 148480;

// stage B smem: WQ hi, KV hi, X hi/lo, Q hi only
constexpr int SB_WQH = 0;
constexpr int SB_KVH = 32768;
constexpr int SB_XH  = 65536;
constexpr int SB_XL  = 81920;
constexpr int SB_QH  = 98304;
constexpr int SB_BQ  = 114688;
constexpr int SB_SMEM = 115200;      // x2 = 230400 <= SM smem
}

__device__ float g_kv[Bb * 128 * 128];

// ---------------------------------------------------------------------------
__device__ __forceinline__ uint32_t smem_u32(const void* p) {
    uint32_t a;
    asm("{ .reg .u64 t; cvta.to.shared.u64 t, %1; cvt.u32.u64 %0, t; }" : "=r"(a) : "l"(p));
    return a;
}
__device__ __forceinline__ uint32_t swz(uint32_t row, uint32_t cb) {
    return row * 256u + (cb & 0x80u) + ((cb & 0x7Fu) ^ ((row & 7u) << 4));
}
__device__ __forceinline__ void ldsm4(uint32_t a, uint32_t* r) {
    asm volatile("ldmatrix.sync.aligned.m8n8.x4.shared.b16 {%0,%1,%2,%3}, [%4];"
        : "=r"(r[0]), "=r"(r[1]), "=r"(r[2]), "=r"(r[3]) : "r"(a));
}
__device__ __forceinline__ void ldsm4t(uint32_t a, uint32_t* r) {
    asm volatile("ldmatrix.sync.aligned.m8n8.x4.trans.shared.b16 {%0,%1,%2,%3}, [%4];"
        : "=r"(r[0]), "=r"(r[1]), "=r"(r[2]), "=r"(r[3]) : "r"(a));
}
__device__ __forceinline__ void mma16816f(float* d, const uint32_t* a, const uint32_t* b) {
    asm volatile(
        "mma.sync.aligned.m16n8k16.row.col.f32.f16.f16.f32 "
        "{%0,%1,%2,%3}, {%4,%5,%6,%7}, {%8,%9}, {%0,%1,%2,%3};"
        : "+f"(d[0]), "+f"(d[1]), "+f"(d[2]), "+f"(d[3])
        : "r"(a[0]), "r"(a[1]), "r"(a[2]), "r"(a[3]), "r"(b[0]), "r"(b[1]));
}
// 2-pass (A hi+lo) 16x16
__device__ __forceinline__ void mma2(float* d0, float* d1,
    const uint32_t* ah, const uint32_t* al, const uint32_t* bh) {
    mma16816f(d0, ah, bh); mma16816f(d1, ah, bh + 2);
    mma16816f(d0, al, bh); mma16816f(d1, al, bh + 2);
}
// 1-pass (A hi) 16x16
__device__ __forceinline__ void mma1(float* d0, float* d1,
    const uint32_t* ah, const uint32_t* bh) {
    mma16816f(d0, ah, bh); mma16816f(d1, ah, bh + 2);
}

__device__ __forceinline__ void split2pack16(float v0, float v1, uint32_t& hp, uint32_t& lp) {
    __half2 h = __floats2half2_rn(v0, v1);
    float2 hf = __half22float2(h);
    __half2 l = __floats2half2_rn(v0 - hf.x, v1 - hf.y);
    hp = *reinterpret_cast<uint32_t*>(&h);
    lp = *reinterpret_cast<uint32_t*>(&l);
}
__device__ __forceinline__ uint32_t pack16(float v0, float v1) {
    __half2 h = __floats2half2_rn(v0, v1);
    return *reinterpret_cast<uint32_t*>(&h);
}

__device__ __forceinline__ float fexp(float x) {
    float t = x * 1.4426950408889634f;
    float r = t + 12582912.0f;
    int   e = __float_as_int(r) - 0x4B400000;
    float y = (t - (r - 12582912.0f)) * 0.6931471805599453f;
    float p = 1.38888894e-3f;
    p = fmaf(p, y, 8.33333377e-3f);
    p = fmaf(p, y, 4.16666679e-2f);
    p = fmaf(p, y, 1.66666672e-1f);
    p = fmaf(p, y, 0.5f);
    p = fmaf(p, y, 1.0f);
    p = fmaf(p, y, 1.0f);
    return __int_as_float(__float_as_int(p) + (e << 23));
}

__global__ void zero_kv_kernel() {
    int i = blockIdx.x * blockDim.x + threadIdx.x;
    reinterpret_cast<float4*>(g_kv)[i] = make_float4(0.f, 0.f, 0.f, 0.f);
}

// prefetched x regs (64x128 fp32 tile) -> fp16 hi/lo swizzled smem
__device__ __forceinline__ void store_x_regs(
    char* smem, int XHo, int XLo, const float4* xr, int tid)
{
    #pragma unroll
    for (int ii = 0; ii < 8; ++ii) {
        int i = tid + ii * 256;
        uint32_t r  = (uint32_t)(i >> 5);
        uint32_t cb = (uint32_t)(i & 31) * 8;
        float4 v = xr[ii];
        uint32_t hp0, lp0, hp1, lp1;
        split2pack16(v.x, v.y, hp0, lp0);
        split2pack16(v.z, v.w, hp1, lp1);
        *(uint2*)(smem + XHo + swz(r, cb)) = make_uint2(hp0, hp1);
        *(uint2*)(smem + XLo + swz(r, cb)) = make_uint2(lp0, lp1);
    }
}

// ===========================================================================
// Stage A
// ===========================================================================
__global__ void __launch_bounds__(256, 1) stageA(
    const float* __restrict__ x,
    const float* __restrict__ Wk, const float* __restrict__ bk,
    const float* __restrict__ Wv, const float* __restrict__ bv)
{
    extern __shared__ char smem[];
    const uint32_t sb = smem_u32(smem);
    const int tid = threadIdx.x, warp = tid >> 5, lane = tid & 31;

    const int task0 = (int)((long)blockIdx.x * TASKS / GRIDA);
    const int task1 = (int)((long)(blockIdx.x + 1) * TASKS / GRIDA);

    // W (hi only) into swizzled smem
    {
        const float2* wk2 = reinterpret_cast<const float2*>(Wk);
        const float2* wv2 = reinterpret_cast<const float2*>(Wv);
        for (int i = tid; i < 8192; i += 256) {
            uint32_t f  = (uint32_t)(i >> 6);
            uint32_t cb = (uint32_t)(i & 63) * 4;
            float2 a = wk2[i];
            *(uint32_t*)(smem + SA_WKH + swz(f, cb)) = pack16(a.x, a.y);
            a = wv2[i];
            *(uint32_t*)(smem + SA_WVH + swz(f, cb)) = pack16(a.x, a.y);
        }
        if (tid < 128) {
            ((float*)(smem + SA_BK))[tid] = bk[tid];
            ((float*)(smem + SA_BV))[tid] = bv[tid];
        }
    }

    const int pm0 = (warp >> 2) * 32, pc0 = (warp & 3) * 32;
    const int u0  = (warp & 3) * 32,  w0  = (warp >> 2) * 64;
    const int er = lane >> 2, ec = 2 * (lane & 3);

    float kvacc[2][8][4];
    #pragma unroll
    for (int mb = 0; mb < 2; ++mb)
        #pragma unroll
        for (int nb = 0; nb < 8; ++nb)
            kvacc[mb][nb][0] = kvacc[mb][nb][1] = kvacc[mb][nb][2] = kvacc[mb][nb][3] = 0.f;

    const float* sbk = (const float*)(smem + SA_BK);
    const float* sbv = (const float*)(smem + SA_BV);
    const float4* xall = reinterpret_cast<const float4*>(x);

    float4 xr[8];
    #pragma unroll
    for (int ii = 0; ii < 8; ++ii)
        xr[ii] = xall[(size_t)task0 * 2048 + ii * 256 + tid];

    int bcur = task0 >> 7;
    for (int t = task0; t < task1; ++t) {
        const int b = t >> 7;
        if (b != bcur) {
            float* kvb = g_kv + (size_t)bcur * 16384;
            #pragma unroll
            for (int mb = 0; mb < 2; ++mb) {
                int ur = u0 + mb * 16 + er;
                #pragma unroll
                for (int nb = 0; nb < 8; ++nb) {
                    int col = w0 + nb * 8 + ec;
                    atomicAdd(&kvb[ur * 128 + col],           kvacc[mb][nb][0]);
                    atomicAdd(&kvb[ur * 128 + col + 1],       kvacc[mb][nb][1]);
                    atomicAdd(&kvb[(ur + 8) * 128 + col],     kvacc[mb][nb][2]);
                    atomicAdd(&kvb[(ur + 8) * 128 + col + 1], kvacc[mb][nb][3]);
                    kvacc[mb][nb][0] = kvacc[mb][nb][1] = kvacc[mb][nb][2] = kvacc[mb][nb][3] = 0.f;
                }
            }
            bcur = b;
        }

        store_x_regs(smem, SA_XH, SA_XL, xr, tid);
        if (t + 1 < task1) {
            #pragma unroll
            for (int ii = 0; ii < 8; ++ii)
                xr[ii] = xall[(size_t)(t + 1) * 2048 + ii * 256 + tid];
        }
        __syncthreads();   // X ready; all warps done with prior kv phase

        // ---- fused K(2-pass)/V(1-pass) projection, warp tile 32x32 ----
        float ka[2][4][4], va[2][4][4];
        #pragma unroll
        for (int mb = 0; mb < 2; ++mb)
            #pragma unroll
            for (int nb = 0; nb < 4; ++nb) {
                ka[mb][nb][0] = ka[mb][nb][1] = ka[mb][nb][2] = ka[mb][nb][3] = 0.f;
                va[mb][nb][0] = va[mb][nb][1] = va[mb][nb][2] = va[mb][nb][3] = 0.f;
            }
        {
            const uint32_t arow0 = (uint32_t)(pm0 + (lane & 15));
            const uint32_t aco   = (uint32_t)((lane >> 4) & 1) * 16;
            const uint32_t brl   = (uint32_t)(lane & 15);
            #pragma unroll
            for (int ks = 0; ks < 8; ++ks) {
                uint32_t ah[2][4], al[2][4];
                uint32_t acb = (uint32_t)ks * 32 + aco;
                ldsm4(sb + SA_XH + swz(arow0,      acb), ah[0]);
                ldsm4(sb + SA_XH + swz(arow0 + 16, acb), ah[1]);
                ldsm4(sb + SA_XL + swz(arow0,      acb), al[0]);
                ldsm4(sb + SA_XL + swz(arow0 + 16, acb), al[1]);
                #pragma unroll
                for (int ng = 0; ng < 2; ++ng) {
                    uint32_t br  = (uint32_t)ks * 16 + brl;
                    uint32_t bcb = (uint32_t)(pc0 + ng * 16) * 2 + aco;
                    uint32_t bh[4];
                    ldsm4t(sb + SA_WKH + swz(br, bcb), bh);
                    mma2(ka[0][2 * ng], ka[0][2 * ng + 1], ah[0], al[0], bh);
                    mma2(ka[1][2 * ng], ka[1][2 * ng + 1], ah[1], al[1], bh);
                    ldsm4t(sb + SA_WVH + swz(br, bcb), bh);
                    mma1(va[0][2 * ng], va[0][2 * ng + 1], ah[0], bh);
                    mma1(va[1][2 * ng], va[1][2 * ng + 1], ah[1], bh);
                }
            }
        }
        // ---- epilogue: k=exp(.+bk) -> hi/lo; v=.+bv -> hi only ----
        #pragma unroll
        for (int mb = 0; mb < 2; ++mb) {
            int r0 = pm0 + mb * 16 + er;
            #pragma unroll
            for (int nb = 0; nb < 4; ++nb) {
                int col = pc0 + nb * 8 + ec;
                float bk0 = sbk[col], bk1 = sbk[col + 1];
                float bv0 = sbv[col], bv1 = sbv[col + 1];
                uint32_t hp, lp;
                split2pack16(fexp(ka[mb][nb][0] + bk0), fexp(ka[mb][nb][1] + bk1), hp, lp);
                *(uint32_t*)(smem + SA_KH + swz((uint32_t)r0, (uint32_t)col * 2)) = hp;
                *(uint32_t*)(smem + SA_KL + swz((uint32_t)r0, (uint32_t)col * 2)) = lp;
                split2pack16(fexp(ka[mb][nb][2] + bk0), fexp(ka[mb][nb][3] + bk1), hp, lp);
                *(uint32_t*)(smem + SA_KH + swz((uint32_t)(r0 + 8), (uint32_t)col * 2)) = hp;
                *(uint32_t*)(smem + SA_KL + swz((uint32_t)(r0 + 8), (uint32_t)col * 2)) = lp;
                *(uint32_t*)(smem + SA_VH + swz((uint32_t)r0, (uint32_t)col * 2)) =
                    pack16(va[mb][nb][0] + bv0, va[mb][nb][1] + bv1);
                *(uint32_t*)(smem + SA_VH + swz((uint32_t)(r0 + 8), (uint32_t)col * 2)) =
                    pack16(va[mb][nb][2] + bv0, va[mb][nb][3] + bv1);
            }
        }
        __syncthreads();   // K/V ready

        // ---- kv += k^T v (A=k 2-pass), warp tile 32u x 64w ----
        {
            const uint32_t krl = (uint32_t)(((lane >> 4) & 1) * 8 + (lane & 7));
            const uint32_t vco = (uint32_t)((lane >> 4) & 1) * 16;
            #pragma unroll
            for (int ks = 0; ks < 4; ++ks) {
                uint32_t kah[2][4], kal[2][4];
                uint32_t kr = (uint32_t)ks * 16 + krl;
                #pragma unroll
                for (int mb = 0; mb < 2; ++mb) {
                    uint32_t ucb = (uint32_t)(u0 + mb * 16 + ((lane >> 3) & 1) * 8) * 2;
                    ldsm4t(sb + SA_KH + swz(kr, ucb), kah[mb]);
                    ldsm4t(sb + SA_KL + swz(kr, ucb), kal[mb]);
                }
                #pragma unroll
                for (int ng = 0; ng < 4; ++ng) {
                    uint32_t vr  = (uint32_t)(ks * 16 + (lane & 15));
                    uint32_t vcb = (uint32_t)(w0 + ng * 16) * 2 + vco;
                    uint32_t bh[4];
                    ldsm4t(sb + SA_VH + swz(vr, vcb), bh);
                    mma2(kvacc[0][2 * ng], kvacc[0][2 * ng + 1], kah[0], kal[0], bh);
                    mma2(kvacc[1][2 * ng], kvacc[1][2 * ng + 1], kah[1], kal[1], bh);
                }
            }
        }
    }

    // final flush
    {
        float* kvb = g_kv + (size_t)bcur * 16384;
        #pragma unroll
        for (int mb = 0; mb < 2; ++mb) {
            int ur = u0 + mb * 16 + er;
            #pragma unroll
            for (int nb = 0; nb < 8; ++nb) {
                int col = w0 + nb * 8 + ec;
                atomicAdd(&kvb[ur * 128 + col],           kvacc[mb][nb][0]);
                atomicAdd(&kvb[ur * 128 + col + 1],       kvacc[mb][nb][1]);
                atomicAdd(&kvb[(ur + 8) * 128 + col],     kvacc[mb][nb][2]);
                atomicAdd(&kvb[(ur + 8) * 128 + col + 1], kvacc[mb][nb][3]);
            }
        }
    }
}

// ===========================================================================
// Stage B — 2 CTAs/SM target
// ===========================================================================
__global__ void __launch_bounds__(256, 2) stageB(
    const float* __restrict__ x,
    const float* __restrict__ Wq, const float* __restrict__ bq,
    float* __restrict__ out)
{
    extern __shared__ char smem[];
    const uint32_t sb = smem_u32(smem);
    const int tid = threadIdx.x, warp = tid >> 5, lane = tid & 31;

    const int task0 = (int)((long)blockIdx.x * TASKS / GRIDB);
    const int task1 = (int)((long)(blockIdx.x + 1) * TASKS / GRIDB);

    {
        const float2* wq2 = reinterpret_cast<const float2*>(Wq);
        for (int i = tid; i < 8192; i += 256) {
            uint32_t f  = (uint32_t)(i >> 6);
            uint32_t cb = (uint32_t)(i & 63) * 4;
            float2 a = wq2[i];
            *(uint32_t*)(smem + SB_WQH + swz(f, cb)) = pack16(a.x, a.y);
        }
        if (tid < 128)
            ((float*)(smem + SB_BQ))[tid] = bq[tid];
    }

    const int m0 = (warp >> 2) * 32, c0 = (warp & 3) * 32;
    const int er = lane >> 2, ec = 2 * (lane & 3);
    const float* sbq = (const float*)(smem + SB_BQ);
    const float4* xall = reinterpret_cast<const float4*>(x);

    float4 xr[8];
    #pragma unroll
    for (int ii = 0; ii < 8; ++ii)
        xr[ii] = xall[(size_t)task0 * 2048 + ii * 256 + tid];

    int bcur = -1;
    for (int t = task0; t < task1; ++t) {
        const int b = t >> 7;

        store_x_regs(smem, SB_XH, SB_XL, xr, tid);
        if (t + 1 < task1) {
            #pragma unroll
            for (int ii = 0; ii < 8; ++ii)
                xr[ii] = xall[(size_t)(t + 1) * 2048 + ii * 256 + tid];
        }
        __syncthreads();   // X ready; all warps past prior out phase

        if (b != bcur) {   // (re)load kv tile (hi only); visibility via next sync
            const float2* kv2 = reinterpret_cast<const float2*>(g_kv) + (size_t)b * 8192;
            for (int i = tid; i < 8192; i += 256) {
                uint32_t f  = (uint32_t)(i >> 6);
                uint32_t cb = (uint32_t)(i & 63) * 4;
                float2 a = kv2[i];
                *(uint32_t*)(smem + SB_KVH + swz(f, cb)) = pack16(a.x, a.y);
            }
            bcur = b;
        }

        // ---- q projection (2-pass), warp tile 32x32 ----
        float pa[2][4][4];
        #pragma unroll
        for (int mb = 0; mb < 2; ++mb)
            #pragma unroll
            for (int nb = 0; nb < 4; ++nb)
                pa[mb][nb][0] = pa[mb][nb][1] = pa[mb][nb][2] = pa[mb][nb][3] = 0.f;
        {
            const uint32_t arow0 = (uint32_t)(m0 + (lane & 15));
            const uint32_t aco   = (uint32_t)((lane >> 4) & 1) * 16;
            const uint32_t brl   = (uint32_t)(lane & 15);
            #pragma unroll
            for (int ks = 0; ks < 8; ++ks) {
                uint32_t ah[2][4], al[2][4];
                uint32_t acb = (uint32_t)ks * 32 + aco;
                ldsm4(sb + SB_XH + swz(arow0,      acb), ah[0]);
                ldsm4(sb + SB_XH + swz(arow0 + 16, acb), ah[1]);
                ldsm4(sb + SB_XL + swz(arow0,      acb), al[0]);
                ldsm4(sb + SB_XL + swz(arow0 + 16, acb), al[1]);
                #pragma unroll
                for (int ng = 0; ng < 2; ++ng) {
                    uint32_t br  = (uint32_t)ks * 16 + brl;
                    uint32_t bcb = (uint32_t)(c0 + ng * 16) * 2 + aco;
                    uint32_t bh[4];
                    ldsm4t(sb + SB_WQH + swz(br, bcb), bh);
                    mma2(pa[0][2 * ng], pa[0][2 * ng + 1], ah[0], al[0], bh);
                    mma2(pa[1][2 * ng], pa[1][2 * ng + 1], ah[1], al[1], bh);
                }
            }
        }
        // ---- epilogue: q = exp(.+bq) -> hi only ----
        #pragma unroll
        for (int mb = 0; mb < 2; ++mb) {
            int r0 = m0 + mb * 16 + er;
            #pragma unroll
            for (int nb = 0; nb < 4; ++nb) {
                int col = c0 + nb * 8 + ec;
                float b0 = sbq[col], b1 = sbq[col + 1];
                *(uint32_t*)(smem + SB_QH + swz((uint32_t)r0, (uint32_t)col * 2)) =
                    pack16(fexp(pa[mb][nb][0] + b0), fexp(pa[mb][nb][1] + b1));
                *(uint32_t*)(smem + SB_QH + swz((uint32_t)(r0 + 8), (uint32_t)col * 2)) =
                    pack16(fexp(pa[mb][nb][2] + b0), fexp(pa[mb][nb][3] + b1));
            }
        }
        __syncthreads();   // Q (and any reloaded KV) ready

        // ---- out = q @ kv (1-pass), warp tile 32x32 ----
        float oa[2][4][4];
        #pragma unroll
        for (int mb = 0; mb < 2; ++mb)
            #pragma unroll
            for (int nb = 0; nb < 4; ++nb)
                oa[mb][nb][0] = oa[mb][nb][1] = oa[mb][nb][2] = oa[mb][nb][3] = 0.f;
        {
            const uint32_t arow0 = (uint32_t)(m0 + (lane & 15));
            const uint32_t aco   = (uint32_t)((lane >> 4) & 1) * 16;
            const uint32_t brl   = (uint32_t)(lane & 15);
            #pragma unroll
            for (int ks = 0; ks < 8; ++ks) {
                uint32_t ah[2][4];
                uint32_t acb = (uint32_t)ks * 32 + aco;
                ldsm4(sb + SB_QH + swz(arow0,      acb), ah[0]);
                ldsm4(sb + SB_QH + swz(arow0 + 16, acb), ah[1]);
                #pragma unroll
                for (int ng = 0; ng < 2; ++ng) {
                    uint32_t br  = (uint32_t)ks * 16 + brl;
                    uint32_t bcb = (uint32_t)(c0 + ng * 16) * 2 + aco;
                    uint32_t bh[4];
                    ldsm4t(sb + SB_KVH + swz(br, bcb), bh);
                    mma1(oa[0][2 * ng], oa[0][2 * ng + 1], ah[0], bh);
                    mma1(oa[1][2 * ng], oa[1][2 * ng + 1], ah[1], bh);
                }
            }
        }
        // store
        float* og = out + (size_t)t * 8192;
        #pragma unroll
        for (int mb = 0; mb < 2; ++mb) {
            int r0 = m0 + mb * 16 + er;
            #pragma unroll
            for (int nb = 0; nb < 4; ++nb) {
                int col = c0 + nb * 8 + ec;
                *(float2*)(og + (size_t)r0 * 128 + col)       = make_float2(oa[mb][nb][0], oa[mb][nb][1]);
                *(float2*)(og + (size_t)(r0 + 8) * 128 + col) = make_float2(oa[mb][nb][2], oa[mb][nb][3]);
            }
        }
    }
}

// ---------------------------------------------------------------------------
extern "C" void kernel_launch(void* const* d_in, const int* in_sizes, int n_in,
                              void* d_out, int out_size) {
    const float* x  = (const float*)d_in[0];
    const float* Wq = (const float*)d_in[1];
    const float* bq = (const float*)d_in[2];
    const float* Wk = (const float*)d_in[3];
    const float* bk = (const float*)d_in[4];
    const float* Wv = (const float*)d_in[5];
    const float* bv = (const float*)d_in[6];
    float* out = (float*)d_out;
    (void)in_sizes; (void)n_in; (void)out_size;

    cudaFuncSetAttribute(stageA, cudaFuncAttributeMaxDynamicSharedMemorySize, SA_SMEM);
    cudaFuncSetAttribute(stageB, cudaFuncAttributeMaxDynamicSharedMemorySize, SB_SMEM);

    zero_kv_kernel<<<256, 256>>>();
    stageA<<<GRIDA, 256, SA_SMEM>>>(x, Wk, bk, Wv, bv);
    stageB<<<GRIDB, 256, SB_SMEM>>>(x, Wq, bq, out);
}

// round 12
// speedup vs baseline: 1.7574x; 1.0798x over previous
#include <cuda_runtime.h>
#include <cuda_fp16.h>
#include <cstdint>

// ============================================================================
// LinearAttentionLayer B=16,N=8192,F=128,U=128 fp32.
// Round 12: kv GEMM -> 1-pass (k hi-only; v and kv are already fp16-rounded
// downstream, so the kl term was wasted precision). Stage A: -20% MMAs,
// KL buffer deleted (smem 132KB). Everything else = round-11 champion:
//   K,Q projections 2-pass (xh+xl); V proj / out GEMM 1-pass;
//   stage B 2 CTAs/SM (grid 296), prefetch, 148-CTA task split.
// ============================================================================

namespace {
constexpr int Bb = 16, Nn = 8192;
constexpr int SUBT = 64;
constexpr int TASKS = Bb * (Nn / SUBT);   // 2048
constexpr int GRIDA = 148;
constexpr int GRIDB = 296;                // 2 CTAs/SM

// stage A smem (bytes)
constexpr int SA_WKH = 0;            // 128x128 fp16 = 32768
constexpr int SA_WVH = 32768;
constexpr int SA_XH  = 65536;        // 64x128 fp16 = 16384
constexpr int SA_XL  = 81920;
constexpr int SA_KH  = 98304;        // hi only now
constexpr int SA_VH  = 114688;
constexpr int SA_BK  = 131072, SA_BV = 131584;
constexpr int SA_SMEM = 132096;

// stage B smem: WQ hi, KV hi, X hi/lo, Q hi only
constexpr int SB_WQH = 0;
constexpr int SB_KVH = 32768;
constexpr int SB_XH  = 65536;
constexpr int SB_XL  = 81920;
constexpr int SB_QH  = 98304;
constexpr int SB_BQ  = 114688;
constexpr int SB_SMEM = 115200;      // x2 = 230400 <= SM smem
}

__device__ float g_kv[Bb * 128 * 128];

// ---------------------------------------------------------------------------
__device__ __forceinline__ uint32_t smem_u32(const void* p) {
    uint32_t a;
    asm("{ .reg .u64 t; cvta.to.shared.u64 t, %1; cvt.u32.u64 %0, t; }" : "=r"(a) : "l"(p));
    return a;
}
__device__ __forceinline__ uint32_t swz(uint32_t row, uint32_t cb) {
    return row * 256u + (cb & 0x80u) + ((cb & 0x7Fu) ^ ((row & 7u) << 4));
}
__device__ __forceinline__ void ldsm4(uint32_t a, uint32_t* r) {
    asm volatile("ldmatrix.sync.aligned.m8n8.x4.shared.b16 {%0,%1,%2,%3}, [%4];"
        : "=r"(r[0]), "=r"(r[1]), "=r"(r[2]), "=r"(r[3]) : "r"(a));
}
__device__ __forceinline__ void ldsm4t(uint32_t a, uint32_t* r) {
    asm volatile("ldmatrix.sync.aligned.m8n8.x4.trans.shared.b16 {%0,%1,%2,%3}, [%4];"
        : "=r"(r[0]), "=r"(r[1]), "=r"(r[2]), "=r"(r[3]) : "r"(a));
}
__device__ __forceinline__ void mma16816f(float* d, const uint32_t* a, const uint32_t* b) {
    asm volatile(
        "mma.sync.aligned.m16n8k16.row.col.f32.f16.f16.f32 "
        "{%0,%1,%2,%3}, {%4,%5,%6,%7}, {%8,%9}, {%0,%1,%2,%3};"
        : "+f"(d[0]), "+f"(d[1]), "+f"(d[2]), "+f"(d[3])
        : "r"(a[0]), "r"(a[1]), "r"(a[2]), "r"(a[3]), "r"(b[0]), "r"(b[1]));
}
// 2-pass (A hi+lo) 16x16
__device__ __forceinline__ void mma2(float* d0, float* d1,
    const uint32_t* ah, const uint32_t* al, const uint32_t* bh) {
    mma16816f(d0, ah, bh); mma16816f(d1, ah, bh + 2);
    mma16816f(d0, al, bh); mma16816f(d1, al, bh + 2);
}
// 1-pass (A hi) 16x16
__device__ __forceinline__ void mma1(float* d0, float* d1,
    const uint32_t* ah, const uint32_t* bh) {
    mma16816f(d0, ah, bh); mma16816f(d1, ah, bh + 2);
}

__device__ __forceinline__ void split2pack16(float v0, float v1, uint32_t& hp, uint32_t& lp) {
    __half2 h = __floats2half2_rn(v0, v1);
    float2 hf = __half22float2(h);
    __half2 l = __floats2half2_rn(v0 - hf.x, v1 - hf.y);
    hp = *reinterpret_cast<uint32_t*>(&h);
    lp = *reinterpret_cast<uint32_t*>(&l);
}
__device__ __forceinline__ uint32_t pack16(float v0, float v1) {
    __half2 h = __floats2half2_rn(v0, v1);
    return *reinterpret_cast<uint32_t*>(&h);
}

__device__ __forceinline__ float fexp(float x) {
    float t = x * 1.4426950408889634f;
    float r = t + 12582912.0f;
    int   e = __float_as_int(r) - 0x4B400000;
    float y = (t - (r - 12582912.0f)) * 0.6931471805599453f;
    float p = 1.38888894e-3f;
    p = fmaf(p, y, 8.33333377e-3f);
    p = fmaf(p, y, 4.16666679e-2f);
    p = fmaf(p, y, 1.66666672e-1f);
    p = fmaf(p, y, 0.5f);
    p = fmaf(p, y, 1.0f);
    p = fmaf(p, y, 1.0f);
    return __int_as_float(__float_as_int(p) + (e << 23));
}

__global__ void zero_kv_kernel() {
    int i = blockIdx.x * blockDim.x + threadIdx.x;
    reinterpret_cast<float4*>(g_kv)[i] = make_float4(0.f, 0.f, 0.f, 0.f);
}

// prefetched x regs (64x128 fp32 tile) -> fp16 hi/lo swizzled smem
__device__ __forceinline__ void store_x_regs(
    char* smem, int XHo, int XLo, const float4* xr, int tid)
{
    #pragma unroll
    for (int ii = 0; ii < 8; ++ii) {
        int i = tid + ii * 256;
        uint32_t r  = (uint32_t)(i >> 5);
        uint32_t cb = (uint32_t)(i & 31) * 8;
        float4 v = xr[ii];
        uint32_t hp0, lp0, hp1, lp1;
        split2pack16(v.x, v.y, hp0, lp0);
        split2pack16(v.z, v.w, hp1, lp1);
        *(uint2*)(smem + XHo + swz(r, cb)) = make_uint2(hp0, hp1);
        *(uint2*)(smem + XLo + swz(r, cb)) = make_uint2(lp0, lp1);
    }
}

// ===========================================================================
// Stage A
// ===========================================================================
__global__ void __launch_bounds__(256, 1) stageA(
    const float* __restrict__ x,
    const float* __restrict__ Wk, const float* __restrict__ bk,
    const float* __restrict__ Wv, const float* __restrict__ bv)
{
    extern __shared__ char smem[];
    const uint32_t sb = smem_u32(smem);
    const int tid = threadIdx.x, warp = tid >> 5, lane = tid & 31;

    const int task0 = (int)((long)blockIdx.x * TASKS / GRIDA);
    const int task1 = (int)((long)(blockIdx.x + 1) * TASKS / GRIDA);

    // W (hi only) into swizzled smem
    {
        const float2* wk2 = reinterpret_cast<const float2*>(Wk);
        const float2* wv2 = reinterpret_cast<const float2*>(Wv);
        for (int i = tid; i < 8192; i += 256) {
            uint32_t f  = (uint32_t)(i >> 6);
            uint32_t cb = (uint32_t)(i & 63) * 4;
            float2 a = wk2[i];
            *(uint32_t*)(smem + SA_WKH + swz(f, cb)) = pack16(a.x, a.y);
            a = wv2[i];
            *(uint32_t*)(smem + SA_WVH + swz(f, cb)) = pack16(a.x, a.y);
        }
        if (tid < 128) {
            ((float*)(smem + SA_BK))[tid] = bk[tid];
            ((float*)(smem + SA_BV))[tid] = bv[tid];
        }
    }

    const int pm0 = (warp >> 2) * 32, pc0 = (warp & 3) * 32;
    const int u0  = (warp & 3) * 32,  w0  = (warp >> 2) * 64;
    const int er = lane >> 2, ec = 2 * (lane & 3);

    float kvacc[2][8][4];
    #pragma unroll
    for (int mb = 0; mb < 2; ++mb)
        #pragma unroll
        for (int nb = 0; nb < 8; ++nb)
            kvacc[mb][nb][0] = kvacc[mb][nb][1] = kvacc[mb][nb][2] = kvacc[mb][nb][3] = 0.f;

    const float* sbk = (const float*)(smem + SA_BK);
    const float* sbv = (const float*)(smem + SA_BV);
    const float4* xall = reinterpret_cast<const float4*>(x);

    float4 xr[8];
    #pragma unroll
    for (int ii = 0; ii < 8; ++ii)
        xr[ii] = xall[(size_t)task0 * 2048 + ii * 256 + tid];

    int bcur = task0 >> 7;
    for (int t = task0; t < task1; ++t) {
        const int b = t >> 7;
        if (b != bcur) {
            float* kvb = g_kv + (size_t)bcur * 16384;
            #pragma unroll
            for (int mb = 0; mb < 2; ++mb) {
                int ur = u0 + mb * 16 + er;
                #pragma unroll
                for (int nb = 0; nb < 8; ++nb) {
                    int col = w0 + nb * 8 + ec;
                    atomicAdd(&kvb[ur * 128 + col],           kvacc[mb][nb][0]);
                    atomicAdd(&kvb[ur * 128 + col + 1],       kvacc[mb][nb][1]);
                    atomicAdd(&kvb[(ur + 8) * 128 + col],     kvacc[mb][nb][2]);
                    atomicAdd(&kvb[(ur + 8) * 128 + col + 1], kvacc[mb][nb][3]);
                    kvacc[mb][nb][0] = kvacc[mb][nb][1] = kvacc[mb][nb][2] = kvacc[mb][nb][3] = 0.f;
                }
            }
            bcur = b;
        }

        store_x_regs(smem, SA_XH, SA_XL, xr, tid);
        if (t + 1 < task1) {
            #pragma unroll
            for (int ii = 0; ii < 8; ++ii)
                xr[ii] = xall[(size_t)(t + 1) * 2048 + ii * 256 + tid];
        }
        __syncthreads();   // X ready; all warps done with prior kv phase

        // ---- fused K(2-pass)/V(1-pass) projection, warp tile 32x32 ----
        float ka[2][4][4], va[2][4][4];
        #pragma unroll
        for (int mb = 0; mb < 2; ++mb)
            #pragma unroll
            for (int nb = 0; nb < 4; ++nb) {
                ka[mb][nb][0] = ka[mb][nb][1] = ka[mb][nb][2] = ka[mb][nb][3] = 0.f;
                va[mb][nb][0] = va[mb][nb][1] = va[mb][nb][2] = va[mb][nb][3] = 0.f;
            }
        {
            const uint32_t arow0 = (uint32_t)(pm0 + (lane & 15));
            const uint32_t aco   = (uint32_t)((lane >> 4) & 1) * 16;
            const uint32_t brl   = (uint32_t)(lane & 15);
            #pragma unroll
            for (int ks = 0; ks < 8; ++ks) {
                uint32_t ah[2][4], al[2][4];
                uint32_t acb = (uint32_t)ks * 32 + aco;
                ldsm4(sb + SA_XH + swz(arow0,      acb), ah[0]);
                ldsm4(sb + SA_XH + swz(arow0 + 16, acb), ah[1]);
                ldsm4(sb + SA_XL + swz(arow0,      acb), al[0]);
                ldsm4(sb + SA_XL + swz(arow0 + 16, acb), al[1]);
                #pragma unroll
                for (int ng = 0; ng < 2; ++ng) {
                    uint32_t br  = (uint32_t)ks * 16 + brl;
                    uint32_t bcb = (uint32_t)(pc0 + ng * 16) * 2 + aco;
                    uint32_t bh[4];
                    ldsm4t(sb + SA_WKH + swz(br, bcb), bh);
                    mma2(ka[0][2 * ng], ka[0][2 * ng + 1], ah[0], al[0], bh);
                    mma2(ka[1][2 * ng], ka[1][2 * ng + 1], ah[1], al[1], bh);
                    ldsm4t(sb + SA_WVH + swz(br, bcb), bh);
                    mma1(va[0][2 * ng], va[0][2 * ng + 1], ah[0], bh);
                    mma1(va[1][2 * ng], va[1][2 * ng + 1], ah[1], bh);
                }
            }
        }
        // ---- epilogue: k=exp(.+bk) -> hi only; v=.+bv -> hi only ----
        #pragma unroll
        for (int mb = 0; mb < 2; ++mb) {
            int r0 = pm0 + mb * 16 + er;
            #pragma unroll
            for (int nb = 0; nb < 4; ++nb) {
                int col = pc0 + nb * 8 + ec;
                float bk0 = sbk[col], bk1 = sbk[col + 1];
                float bv0 = sbv[col], bv1 = sbv[col + 1];
                *(uint32_t*)(smem + SA_KH + swz((uint32_t)r0, (uint32_t)col * 2)) =
                    pack16(fexp(ka[mb][nb][0] + bk0), fexp(ka[mb][nb][1] + bk1));
                *(uint32_t*)(smem + SA_KH + swz((uint32_t)(r0 + 8), (uint32_t)col * 2)) =
                    pack16(fexp(ka[mb][nb][2] + bk0), fexp(ka[mb][nb][3] + bk1));
                *(uint32_t*)(smem + SA_VH + swz((uint32_t)r0, (uint32_t)col * 2)) =
                    pack16(va[mb][nb][0] + bv0, va[mb][nb][1] + bv1);
                *(uint32_t*)(smem + SA_VH + swz((uint32_t)(r0 + 8), (uint32_t)col * 2)) =
                    pack16(va[mb][nb][2] + bv0, va[mb][nb][3] + bv1);
            }
        }
        __syncthreads();   // K/V ready

        // ---- kv += k^T v (1-pass), warp tile 32u x 64w ----
        {
            const uint32_t krl = (uint32_t)(((lane >> 4) & 1) * 8 + (lane & 7));
            const uint32_t vco = (uint32_t)((lane >> 4) & 1) * 16;
            #pragma unroll
            for (int ks = 0; ks < 4; ++ks) {
                uint32_t kah[2][4];
                uint32_t kr = (uint32_t)ks * 16 + krl;
                #pragma unroll
                for (int mb = 0; mb < 2; ++mb) {
                    uint32_t ucb = (uint32_t)(u0 + mb * 16 + ((lane >> 3) & 1) * 8) * 2;
                    ldsm4t(sb + SA_KH + swz(kr, ucb), kah[mb]);
                }
                #pragma unroll
                for (int ng = 0; ng < 4; ++ng) {
                    uint32_t vr  = (uint32_t)(ks * 16 + (lane & 15));
                    uint32_t vcb = (uint32_t)(w0 + ng * 16) * 2 + vco;
                    uint32_t bh[4];
                    ldsm4t(sb + SA_VH + swz(vr, vcb), bh);
                    mma1(kvacc[0][2 * ng], kvacc[0][2 * ng + 1], kah[0], bh);
                    mma1(kvacc[1][2 * ng], kvacc[1][2 * ng + 1], kah[1], bh);
                }
            }
        }
    }

    // final flush
    {
        float* kvb = g_kv + (size_t)bcur * 16384;
        #pragma unroll
        for (int mb = 0; mb < 2; ++mb) {
            int ur = u0 + mb * 16 + er;
            #pragma unroll
            for (int nb = 0; nb < 8; ++nb) {
                int col = w0 + nb * 8 + ec;
                atomicAdd(&kvb[ur * 128 + col],           kvacc[mb][nb][0]);
                atomicAdd(&kvb[ur * 128 + col + 1],       kvacc[mb][nb][1]);
                atomicAdd(&kvb[(ur + 8) * 128 + col],     kvacc[mb][nb][2]);
                atomicAdd(&kvb[(ur + 8) * 128 + col + 1], kvacc[mb][nb][3]);
            }
        }
    }
}

// ===========================================================================
// Stage B — 2 CTAs/SM
// ===========================================================================
__global__ void __launch_bounds__(256, 2) stageB(
    const float* __restrict__ x,
    const float* __restrict__ Wq, const float* __restrict__ bq,
    float* __restrict__ out)
{
    extern __shared__ char smem[];
    const uint32_t sb = smem_u32(smem);
    const int tid = threadIdx.x, warp = tid >> 5, lane = tid & 31;

    const int task0 = (int)((long)blockIdx.x * TASKS / GRIDB);
    const int task1 = (int)((long)(blockIdx.x + 1) * TASKS / GRIDB);

    {
        const float2* wq2 = reinterpret_cast<const float2*>(Wq);
        for (int i = tid; i < 8192; i += 256) {
            uint32_t f  = (uint32_t)(i >> 6);
            uint32_t cb = (uint32_t)(i & 63) * 4;
            float2 a = wq2[i];
            *(uint32_t*)(smem + SB_WQH + swz(f, cb)) = pack16(a.x, a.y);
        }
        if (tid < 128)
            ((float*)(smem + SB_BQ))[tid] = bq[tid];
    }

    const int m0 = (warp >> 2) * 32, c0 = (warp & 3) * 32;
    const int er = lane >> 2, ec = 2 * (lane & 3);
    const float* sbq = (const float*)(smem + SB_BQ);
    const float4* xall = reinterpret_cast<const float4*>(x);

    float4 xr[8];
    #pragma unroll
    for (int ii = 0; ii < 8; ++ii)
        xr[ii] = xall[(size_t)task0 * 2048 + ii * 256 + tid];

    int bcur = -1;
    for (int t = task0; t < task1; ++t) {
        const int b = t >> 7;

        store_x_regs(smem, SB_XH, SB_XL, xr, tid);
        if (t + 1 < task1) {
            #pragma unroll
            for (int ii = 0; ii < 8; ++ii)
                xr[ii] = xall[(size_t)(t + 1) * 2048 + ii * 256 + tid];
        }
        __syncthreads();   // X ready; all warps past prior out phase

        if (b != bcur) {   // (re)load kv tile (hi only); visibility via next sync
            const float2* kv2 = reinterpret_cast<const float2*>(g_kv) + (size_t)b * 8192;
            for (int i = tid; i < 8192; i += 256) {
                uint32_t f  = (uint32_t)(i >> 6);
                uint32_t cb = (uint32_t)(i & 63) * 4;
                float2 a = kv2[i];
                *(uint32_t*)(smem + SB_KVH + swz(f, cb)) = pack16(a.x, a.y);
            }
            bcur = b;
        }

        // ---- q projection (2-pass), warp tile 32x32 ----
        float pa[2][4][4];
        #pragma unroll
        for (int mb = 0; mb < 2; ++mb)
            #pragma unroll
            for (int nb = 0; nb < 4; ++nb)
                pa[mb][nb][0] = pa[mb][nb][1] = pa[mb][nb][2] = pa[mb][nb][3] = 0.f;
        {
            const uint32_t arow0 = (uint32_t)(m0 + (lane & 15));
            const uint32_t aco   = (uint32_t)((lane >> 4) & 1) * 16;
            const uint32_t brl   = (uint32_t)(lane & 15);
            #pragma unroll
            for (int ks = 0; ks < 8; ++ks) {
                uint32_t ah[2][4], al[2][4];
                uint32_t acb = (uint32_t)ks * 32 + aco;
                ldsm4(sb + SB_XH + swz(arow0,      acb), ah[0]);
                ldsm4(sb + SB_XH + swz(arow0 + 16, acb), ah[1]);
                ldsm4(sb + SB_XL + swz(arow0,      acb), al[0]);
                ldsm4(sb + SB_XL + swz(arow0 + 16, acb), al[1]);
                #pragma unroll
                for (int ng = 0; ng < 2; ++ng) {
                    uint32_t br  = (uint32_t)ks * 16 + brl;
                    uint32_t bcb = (uint32_t)(c0 + ng * 16) * 2 + aco;
                    uint32_t bh[4];
                    ldsm4t(sb + SB_WQH + swz(br, bcb), bh);
                    mma2(pa[0][2 * ng], pa[0][2 * ng + 1], ah[0], al[0], bh);
                    mma2(pa[1][2 * ng], pa[1][2 * ng + 1], ah[1], al[1], bh);
                }
            }
        }
        // ---- epilogue: q = exp(.+bq) -> hi only ----
        #pragma unroll
        for (int mb = 0; mb < 2; ++mb) {
            int r0 = m0 + mb * 16 + er;
            #pragma unroll
            for (int nb = 0; nb < 4; ++nb) {
                int col = c0 + nb * 8 + ec;
                float b0 = sbq[col], b1 = sbq[col + 1];
                *(uint32_t*)(smem + SB_QH + swz((uint32_t)r0, (uint32_t)col * 2)) =
                    pack16(fexp(pa[mb][nb][0] + b0), fexp(pa[mb][nb][1] + b1));
                *(uint32_t*)(smem + SB_QH + swz((uint32_t)(r0 + 8), (uint32_t)col * 2)) =
                    pack16(fexp(pa[mb][nb][2] + b0), fexp(pa[mb][nb][3] + b1));
            }
        }
        __syncthreads();   // Q (and any reloaded KV) ready

        // ---- out = q @ kv (1-pass), warp tile 32x32 ----
        float oa[2][4][4];
        #pragma unroll
        for (int mb = 0; mb < 2; ++mb)
            #pragma unroll
            for (int nb = 0; nb < 4; ++nb)
                oa[mb][nb][0] = oa[mb][nb][1] = oa[mb][nb][2] = oa[mb][nb][3] = 0.f;
        {
            const uint32_t arow0 = (uint32_t)(m0 + (lane & 15));
            const uint32_t aco   = (uint32_t)((lane >> 4) & 1) * 16;
            const uint32_t brl   = (uint32_t)(lane & 15);
            #pragma unroll
            for (int ks = 0; ks < 8; ++ks) {
                uint32_t ah[2][4];
                uint32_t acb = (uint32_t)ks * 32 + aco;
                ldsm4(sb + SB_QH + swz(arow0,      acb), ah[0]);
                ldsm4(sb + SB_QH + swz(arow0 + 16, acb), ah[1]);
                #pragma unroll
                for (int ng = 0; ng < 2; ++ng) {
                    uint32_t br  = (uint32_t)ks * 16 + brl;
                    uint32_t bcb = (uint32_t)(c0 + ng * 16) * 2 + aco;
                    uint32_t bh[4];
                    ldsm4t(sb + SB_KVH + swz(br, bcb), bh);
                    mma1(oa[0][2 * ng], oa[0][2 * ng + 1], ah[0], bh);
                    mma1(oa[1][2 * ng], oa[1][2 * ng + 1], ah[1], bh);
                }
            }
        }
        // store
        float* og = out + (size_t)t * 8192;
        #pragma unroll
        for (int mb = 0; mb < 2; ++mb) {
            int r0 = m0 + mb * 16 + er;
            #pragma unroll
            for (int nb = 0; nb < 4; ++nb) {
                int col = c0 + nb * 8 + ec;
                *(float2*)(og + (size_t)r0 * 128 + col)       = make_float2(oa[mb][nb][0], oa[mb][nb][1]);
                *(float2*)(og + (size_t)(r0 + 8) * 128 + col) = make_float2(oa[mb][nb][2], oa[mb][nb][3]);
            }
        }
    }
}

// ---------------------------------------------------------------------------
extern "C" void kernel_launch(void* const* d_in, const int* in_sizes, int n_in,
                              void* d_out, int out_size) {
    const float* x  = (const float*)d_in[0];
    const float* Wq = (const float*)d_in[1];
    const float* bq = (const float*)d_in[2];
    const float* Wk = (const float*)d_in[3];
    const float* bk = (const float*)d_in[4];
    const float* Wv = (const float*)d_in[5];
    const float* bv = (const float*)d_in[6];
    float* out = (float*)d_out;
    (void)in_sizes; (void)n_in; (void)out_size;

    cudaFuncSetAttribute(stageA, cudaFuncAttributeMaxDynamicSharedMemorySize, SA_SMEM);
    cudaFuncSetAttribute(stageB, cudaFuncAttributeMaxDynamicSharedMemorySize, SB_SMEM);

    zero_kv_kernel<<<256, 256>>>();
    stageA<<<GRIDA, 256, SA_SMEM>>>(x, Wk, bk, Wv, bv);
    stageB<<<GRIDB, 256, SB_SMEM>>>(x, Wq, bq, out);
}

// round 13
// speedup vs baseline: 2.0986x; 1.1941x over previous
#include <cuda_runtime.h>
#include <cuda_fp16.h>
#include <cstdint>

// ============================================================================
// LinearAttentionLayer B=16,N=8192,F=128,U=128 fp32.
// Round 13: ALL GEMMs single-pass fp16. Round-12's null error delta proved
// the fp16 STORAGE roundings (k,v,q,kv @1.2e-4) dominate; xl lo-terms in the
// K/Q projections protect to 2^-22 what storage then rounds to 2^-12 — waste.
// Drop XL everywhere: -25% stage-A MMAs, -33% stage-B MMAs, half the x LDSM,
// cheaper epilogues, smaller smem (A 115.7KB, B 98.8KB @ 2 CTAs/SM).
// ============================================================================

namespace {
constexpr int Bb = 16, Nn = 8192;
constexpr int SUBT = 64;
constexpr int TASKS = Bb * (Nn / SUBT);   // 2048
constexpr int GRIDA = 148;
constexpr int GRIDB = 296;                // 2 CTAs/SM

// stage A smem (bytes): all hi-only
constexpr int SA_WKH = 0;            // 128x128 fp16 = 32768
constexpr int SA_WVH = 32768;
constexpr int SA_XH  = 65536;        // 64x128 fp16 = 16384
constexpr int SA_KH  = 81920;
constexpr int SA_VH  = 98304;
constexpr int SA_BK  = 114688, SA_BV = 115200;
constexpr int SA_SMEM = 115712;

// stage B smem
constexpr int SB_WQH = 0;
constexpr int SB_KVH = 32768;
constexpr int SB_XH  = 65536;
constexpr int SB_QH  = 81920;
constexpr int SB_BQ  = 98304;
constexpr int SB_SMEM = 98816;       // x2 = 197632, 2 CTAs/SM
}

__device__ float g_kv[Bb * 128 * 128];

// ---------------------------------------------------------------------------
__device__ __forceinline__ uint32_t smem_u32(const void* p) {
    uint32_t a;
    asm("{ .reg .u64 t; cvta.to.shared.u64 t, %1; cvt.u32.u64 %0, t; }" : "=r"(a) : "l"(p));
    return a;
}
__device__ __forceinline__ uint32_t swz(uint32_t row, uint32_t cb) {
    return row * 256u + (cb & 0x80u) + ((cb & 0x7Fu) ^ ((row & 7u) << 4));
}
__device__ __forceinline__ void ldsm4(uint32_t a, uint32_t* r) {
    asm volatile("ldmatrix.sync.aligned.m8n8.x4.shared.b16 {%0,%1,%2,%3}, [%4];"
        : "=r"(r[0]), "=r"(r[1]), "=r"(r[2]), "=r"(r[3]) : "r"(a));
}
__device__ __forceinline__ void ldsm4t(uint32_t a, uint32_t* r) {
    asm volatile("ldmatrix.sync.aligned.m8n8.x4.trans.shared.b16 {%0,%1,%2,%3}, [%4];"
        : "=r"(r[0]), "=r"(r[1]), "=r"(r[2]), "=r"(r[3]) : "r"(a));
}
__device__ __forceinline__ void mma16816f(float* d, const uint32_t* a, const uint32_t* b) {
    asm volatile(
        "mma.sync.aligned.m16n8k16.row.col.f32.f16.f16.f32 "
        "{%0,%1,%2,%3}, {%4,%5,%6,%7}, {%8,%9}, {%0,%1,%2,%3};"
        : "+f"(d[0]), "+f"(d[1]), "+f"(d[2]), "+f"(d[3])
        : "r"(a[0]), "r"(a[1]), "r"(a[2]), "r"(a[3]), "r"(b[0]), "r"(b[1]));
}
// 1-pass 16x16
__device__ __forceinline__ void mma1(float* d0, float* d1,
    const uint32_t* ah, const uint32_t* bh) {
    mma16816f(d0, ah, bh); mma16816f(d1, ah, bh + 2);
}

__device__ __forceinline__ uint32_t pack16(float v0, float v1) {
    __half2 h = __floats2half2_rn(v0, v1);
    return *reinterpret_cast<uint32_t*>(&h);
}

__device__ __forceinline__ float fexp(float x) {
    float t = x * 1.4426950408889634f;
    float r = t + 12582912.0f;
    int   e = __float_as_int(r) - 0x4B400000;
    float y = (t - (r - 12582912.0f)) * 0.6931471805599453f;
    float p = 1.38888894e-3f;
    p = fmaf(p, y, 8.33333377e-3f);
    p = fmaf(p, y, 4.16666679e-2f);
    p = fmaf(p, y, 1.66666672e-1f);
    p = fmaf(p, y, 0.5f);
    p = fmaf(p, y, 1.0f);
    p = fmaf(p, y, 1.0f);
    return __int_as_float(__float_as_int(p) + (e << 23));
}

__global__ void zero_kv_kernel() {
    int i = blockIdx.x * blockDim.x + threadIdx.x;
    reinterpret_cast<float4*>(g_kv)[i] = make_float4(0.f, 0.f, 0.f, 0.f);
}

// prefetched x regs (64x128 fp32 tile) -> fp16 hi swizzled smem
__device__ __forceinline__ void store_x_regs(
    char* smem, int XHo, const float4* xr, int tid)
{
    #pragma unroll
    for (int ii = 0; ii < 8; ++ii) {
        int i = tid + ii * 256;
        uint32_t r  = (uint32_t)(i >> 5);
        uint32_t cb = (uint32_t)(i & 31) * 8;
        float4 v = xr[ii];
        *(uint2*)(smem + XHo + swz(r, cb)) =
            make_uint2(pack16(v.x, v.y), pack16(v.z, v.w));
    }
}

// ===========================================================================
// Stage A
// ===========================================================================
__global__ void __launch_bounds__(256, 1) stageA(
    const float* __restrict__ x,
    const float* __restrict__ Wk, const float* __restrict__ bk,
    const float* __restrict__ Wv, const float* __restrict__ bv)
{
    extern __shared__ char smem[];
    const uint32_t sb = smem_u32(smem);
    const int tid = threadIdx.x, warp = tid >> 5, lane = tid & 31;

    const int task0 = (int)((long)blockIdx.x * TASKS / GRIDA);
    const int task1 = (int)((long)(blockIdx.x + 1) * TASKS / GRIDA);

    // W (hi only) into swizzled smem
    {
        const float2* wk2 = reinterpret_cast<const float2*>(Wk);
        const float2* wv2 = reinterpret_cast<const float2*>(Wv);
        for (int i = tid; i < 8192; i += 256) {
            uint32_t f  = (uint32_t)(i >> 6);
            uint32_t cb = (uint32_t)(i & 63) * 4;
            float2 a = wk2[i];
            *(uint32_t*)(smem + SA_WKH + swz(f, cb)) = pack16(a.x, a.y);
            a = wv2[i];
            *(uint32_t*)(smem + SA_WVH + swz(f, cb)) = pack16(a.x, a.y);
        }
        if (tid < 128) {
            ((float*)(smem + SA_BK))[tid] = bk[tid];
            ((float*)(smem + SA_BV))[tid] = bv[tid];
        }
    }

    const int pm0 = (warp >> 2) * 32, pc0 = (warp & 3) * 32;
    const int u0  = (warp & 3) * 32,  w0  = (warp >> 2) * 64;
    const int er = lane >> 2, ec = 2 * (lane & 3);

    float kvacc[2][8][4];
    #pragma unroll
    for (int mb = 0; mb < 2; ++mb)
        #pragma unroll
        for (int nb = 0; nb < 8; ++nb)
            kvacc[mb][nb][0] = kvacc[mb][nb][1] = kvacc[mb][nb][2] = kvacc[mb][nb][3] = 0.f;

    const float* sbk = (const float*)(smem + SA_BK);
    const float* sbv = (const float*)(smem + SA_BV);
    const float4* xall = reinterpret_cast<const float4*>(x);

    float4 xr[8];
    #pragma unroll
    for (int ii = 0; ii < 8; ++ii)
        xr[ii] = xall[(size_t)task0 * 2048 + ii * 256 + tid];

    int bcur = task0 >> 7;
    for (int t = task0; t < task1; ++t) {
        const int b = t >> 7;
        if (b != bcur) {
            float* kvb = g_kv + (size_t)bcur * 16384;
            #pragma unroll
            for (int mb = 0; mb < 2; ++mb) {
                int ur = u0 + mb * 16 + er;
                #pragma unroll
                for (int nb = 0; nb < 8; ++nb) {
                    int col = w0 + nb * 8 + ec;
                    atomicAdd(&kvb[ur * 128 + col],           kvacc[mb][nb][0]);
                    atomicAdd(&kvb[ur * 128 + col + 1],       kvacc[mb][nb][1]);
                    atomicAdd(&kvb[(ur + 8) * 128 + col],     kvacc[mb][nb][2]);
                    atomicAdd(&kvb[(ur + 8) * 128 + col + 1], kvacc[mb][nb][3]);
                    kvacc[mb][nb][0] = kvacc[mb][nb][1] = kvacc[mb][nb][2] = kvacc[mb][nb][3] = 0.f;
                }
            }
            bcur = b;
        }

        store_x_regs(smem, SA_XH, xr, tid);
        if (t + 1 < task1) {
            #pragma unroll
            for (int ii = 0; ii < 8; ++ii)
                xr[ii] = xall[(size_t)(t + 1) * 2048 + ii * 256 + tid];
        }
        __syncthreads();   // X ready; all warps done with prior kv phase

        // ---- fused K/V projection (1-pass), warp tile 32x32 ----
        float ka[2][4][4], va[2][4][4];
        #pragma unroll
        for (int mb = 0; mb < 2; ++mb)
            #pragma unroll
            for (int nb = 0; nb < 4; ++nb) {
                ka[mb][nb][0] = ka[mb][nb][1] = ka[mb][nb][2] = ka[mb][nb][3] = 0.f;
                va[mb][nb][0] = va[mb][nb][1] = va[mb][nb][2] = va[mb][nb][3] = 0.f;
            }
        {
            const uint32_t arow0 = (uint32_t)(pm0 + (lane & 15));
            const uint32_t aco   = (uint32_t)((lane >> 4) & 1) * 16;
            const uint32_t brl   = (uint32_t)(lane & 15);
            #pragma unroll
            for (int ks = 0; ks < 8; ++ks) {
                uint32_t ah[2][4];
                uint32_t acb = (uint32_t)ks * 32 + aco;
                ldsm4(sb + SA_XH + swz(arow0,      acb), ah[0]);
                ldsm4(sb + SA_XH + swz(arow0 + 16, acb), ah[1]);
                #pragma unroll
                for (int ng = 0; ng < 2; ++ng) {
                    uint32_t br  = (uint32_t)ks * 16 + brl;
                    uint32_t bcb = (uint32_t)(pc0 + ng * 16) * 2 + aco;
                    uint32_t bh[4];
                    ldsm4t(sb + SA_WKH + swz(br, bcb), bh);
                    mma1(ka[0][2 * ng], ka[0][2 * ng + 1], ah[0], bh);
                    mma1(ka[1][2 * ng], ka[1][2 * ng + 1], ah[1], bh);
                    ldsm4t(sb + SA_WVH + swz(br, bcb), bh);
                    mma1(va[0][2 * ng], va[0][2 * ng + 1], ah[0], bh);
                    mma1(va[1][2 * ng], va[1][2 * ng + 1], ah[1], bh);
                }
            }
        }
        // ---- epilogue: k=exp(.+bk), v=.+bv -> hi smem ----
        #pragma unroll
        for (int mb = 0; mb < 2; ++mb) {
            int r0 = pm0 + mb * 16 + er;
            #pragma unroll
            for (int nb = 0; nb < 4; ++nb) {
                int col = pc0 + nb * 8 + ec;
                float bk0 = sbk[col], bk1 = sbk[col + 1];
                float bv0 = sbv[col], bv1 = sbv[col + 1];
                *(uint32_t*)(smem + SA_KH + swz((uint32_t)r0, (uint32_t)col * 2)) =
                    pack16(fexp(ka[mb][nb][0] + bk0), fexp(ka[mb][nb][1] + bk1));
                *(uint32_t*)(smem + SA_KH + swz((uint32_t)(r0 + 8), (uint32_t)col * 2)) =
                    pack16(fexp(ka[mb][nb][2] + bk0), fexp(ka[mb][nb][3] + bk1));
                *(uint32_t*)(smem + SA_VH + swz((uint32_t)r0, (uint32_t)col * 2)) =
                    pack16(va[mb][nb][0] + bv0, va[mb][nb][1] + bv1);
                *(uint32_t*)(smem + SA_VH + swz((uint32_t)(r0 + 8), (uint32_t)col * 2)) =
                    pack16(va[mb][nb][2] + bv0, va[mb][nb][3] + bv1);
            }
        }
        __syncthreads();   // K/V ready

        // ---- kv += k^T v (1-pass), warp tile 32u x 64w ----
        {
            const uint32_t krl = (uint32_t)(((lane >> 4) & 1) * 8 + (lane & 7));
            const uint32_t vco = (uint32_t)((lane >> 4) & 1) * 16;
            #pragma unroll
            for (int ks = 0; ks < 4; ++ks) {
                uint32_t kah[2][4];
                uint32_t kr = (uint32_t)ks * 16 + krl;
                #pragma unroll
                for (int mb = 0; mb < 2; ++mb) {
                    uint32_t ucb = (uint32_t)(u0 + mb * 16 + ((lane >> 3) & 1) * 8) * 2;
                    ldsm4t(sb + SA_KH + swz(kr, ucb), kah[mb]);
                }
                #pragma unroll
                for (int ng = 0; ng < 4; ++ng) {
                    uint32_t vr  = (uint32_t)(ks * 16 + (lane & 15));
                    uint32_t vcb = (uint32_t)(w0 + ng * 16) * 2 + vco;
                    uint32_t bh[4];
                    ldsm4t(sb + SA_VH + swz(vr, vcb), bh);
                    mma1(kvacc[0][2 * ng], kvacc[0][2 * ng + 1], kah[0], bh);
                    mma1(kvacc[1][2 * ng], kvacc[1][2 * ng + 1], kah[1], bh);
                }
            }
        }
    }

    // final flush
    {
        float* kvb = g_kv + (size_t)bcur * 16384;
        #pragma unroll
        for (int mb = 0; mb < 2; ++mb) {
            int ur = u0 + mb * 16 + er;
            #pragma unroll
            for (int nb = 0; nb < 8; ++nb) {
                int col = w0 + nb * 8 + ec;
                atomicAdd(&kvb[ur * 128 + col],           kvacc[mb][nb][0]);
                atomicAdd(&kvb[ur * 128 + col + 1],       kvacc[mb][nb][1]);
                atomicAdd(&kvb[(ur + 8) * 128 + col],     kvacc[mb][nb][2]);
                atomicAdd(&kvb[(ur + 8) * 128 + col + 1], kvacc[mb][nb][3]);
            }
        }
    }
}

// ===========================================================================
// Stage B — 2 CTAs/SM
// ===========================================================================
__global__ void __launch_bounds__(256, 2) stageB(
    const float* __restrict__ x,
    const float* __restrict__ Wq, const float* __restrict__ bq,
    float* __restrict__ out)
{
    extern __shared__ char smem[];
    const uint32_t sb = smem_u32(smem);
    const int tid = threadIdx.x, warp = tid >> 5, lane = tid & 31;

    const int task0 = (int)((long)blockIdx.x * TASKS / GRIDB);
    const int task1 = (int)((long)(blockIdx.x + 1) * TASKS / GRIDB);

    {
        const float2* wq2 = reinterpret_cast<const float2*>(Wq);
        for (int i = tid; i < 8192; i += 256) {
            uint32_t f  = (uint32_t)(i >> 6);
            uint32_t cb = (uint32_t)(i & 63) * 4;
            float2 a = wq2[i];
            *(uint32_t*)(smem + SB_WQH + swz(f, cb)) = pack16(a.x, a.y);
        }
        if (tid < 128)
            ((float*)(smem + SB_BQ))[tid] = bq[tid];
    }

    const int m0 = (warp >> 2) * 32, c0 = (warp & 3) * 32;
    const int er = lane >> 2, ec = 2 * (lane & 3);
    const float* sbq = (const float*)(smem + SB_BQ);
    const float4* xall = reinterpret_cast<const float4*>(x);

    float4 xr[8];
    #pragma unroll
    for (int ii = 0; ii < 8; ++ii)
        xr[ii] = xall[(size_t)task0 * 2048 + ii * 256 + tid];

    int bcur = -1;
    for (int t = task0; t < task1; ++t) {
        const int b = t >> 7;

        store_x_regs(smem, SB_XH, xr, tid);
        if (t + 1 < task1) {
            #pragma unroll
            for (int ii = 0; ii < 8; ++ii)
                xr[ii] = xall[(size_t)(t + 1) * 2048 + ii * 256 + tid];
        }
        __syncthreads();   // X ready; all warps past prior out phase

        if (b != bcur) {   // (re)load kv tile (hi only); visibility via next sync
            const float2* kv2 = reinterpret_cast<const float2*>(g_kv) + (size_t)b * 8192;
            for (int i = tid; i < 8192; i += 256) {
                uint32_t f  = (uint32_t)(i >> 6);
                uint32_t cb = (uint32_t)(i & 63) * 4;
                float2 a = kv2[i];
                *(uint32_t*)(smem + SB_KVH + swz(f, cb)) = pack16(a.x, a.y);
            }
            bcur = b;
        }

        // ---- q projection (1-pass), warp tile 32x32 ----
        float pa[2][4][4];
        #pragma unroll
        for (int mb = 0; mb < 2; ++mb)
            #pragma unroll
            for (int nb = 0; nb < 4; ++nb)
                pa[mb][nb][0] = pa[mb][nb][1] = pa[mb][nb][2] = pa[mb][nb][3] = 0.f;
        {
            const uint32_t arow0 = (uint32_t)(m0 + (lane & 15));
            const uint32_t aco   = (uint32_t)((lane >> 4) & 1) * 16;
            const uint32_t brl   = (uint32_t)(lane & 15);
            #pragma unroll
            for (int ks = 0; ks < 8; ++ks) {
                uint32_t ah[2][4];
                uint32_t acb = (uint32_t)ks * 32 + aco;
                ldsm4(sb + SB_XH + swz(arow0,      acb), ah[0]);
                ldsm4(sb + SB_XH + swz(arow0 + 16, acb), ah[1]);
                #pragma unroll
                for (int ng = 0; ng < 2; ++ng) {
                    uint32_t br  = (uint32_t)ks * 16 + brl;
                    uint32_t bcb = (uint32_t)(c0 + ng * 16) * 2 + aco;
                    uint32_t bh[4];
                    ldsm4t(sb + SB_WQH + swz(br, bcb), bh);
                    mma1(pa[0][2 * ng], pa[0][2 * ng + 1], ah[0], bh);
                    mma1(pa[1][2 * ng], pa[1][2 * ng + 1], ah[1], bh);
                }
            }
        }
        // ---- epilogue: q = exp(.+bq) -> hi only ----
        #pragma unroll
        for (int mb = 0; mb < 2; ++mb) {
            int r0 = m0 + mb * 16 + er;
            #pragma unroll
            for (int nb = 0; nb < 4; ++nb) {
                int col = c0 + nb * 8 + ec;
                float b0 = sbq[col], b1 = sbq[col + 1];
                *(uint32_t*)(smem + SB_QH + swz((uint32_t)r0, (uint32_t)col * 2)) =
                    pack16(fexp(pa[mb][nb][0] + b0), fexp(pa[mb][nb][1] + b1));
                *(uint32_t*)(smem + SB_QH + swz((uint32_t)(r0 + 8), (uint32_t)col * 2)) =
                    pack16(fexp(pa[mb][nb][2] + b0), fexp(pa[mb][nb][3] + b1));
            }
        }
        __syncthreads();   // Q (and any reloaded KV) ready

        // ---- out = q @ kv (1-pass), warp tile 32x32 ----
        float oa[2][4][4];
        #pragma unroll
        for (int mb = 0; mb < 2; ++mb)
            #pragma unroll
            for (int nb = 0; nb < 4; ++nb)
                oa[mb][nb][0] = oa[mb][nb][1] = oa[mb][nb][2] = oa[mb][nb][3] = 0.f;
        {
            const uint32_t arow0 = (uint32_t)(m0 + (lane & 15));
            const uint32_t aco   = (uint32_t)((lane >> 4) & 1) * 16;
            const uint32_t brl   = (uint32_t)(lane & 15);
            #pragma unroll
            for (int ks = 0; ks < 8; ++ks) {
                uint32_t ah[2][4];
                uint32_t acb = (uint32_t)ks * 32 + aco;
                ldsm4(sb + SB_QH + swz(arow0,      acb), ah[0]);
                ldsm4(sb + SB_QH + swz(arow0 + 16, acb), ah[1]);
                #pragma unroll
                for (int ng = 0; ng < 2; ++ng) {
                    uint32_t br  = (uint32_t)ks * 16 + brl;
                    uint32_t bcb = (uint32_t)(c0 + ng * 16) * 2 + aco;
                    uint32_t bh[4];
                    ldsm4t(sb + SB_KVH + swz(br, bcb), bh);
                    mma1(oa[0][2 * ng], oa[0][2 * ng + 1], ah[0], bh);
                    mma1(oa[1][2 * ng], oa[1][2 * ng + 1], ah[1], bh);
                }
            }
        }
        // store
        float* og = out + (size_t)t * 8192;
        #pragma unroll
        for (int mb = 0; mb < 2; ++mb) {
            int r0 = m0 + mb * 16 + er;
            #pragma unroll
            for (int nb = 0; nb < 4; ++nb) {
                int col = c0 + nb * 8 + ec;
                *(float2*)(og + (size_t)r0 * 128 + col)       = make_float2(oa[mb][nb][0], oa[mb][nb][1]);
                *(float2*)(og + (size_t)(r0 + 8) * 128 + col) = make_float2(oa[mb][nb][2], oa[mb][nb][3]);
            }
        }
    }
}

// ---------------------------------------------------------------------------
extern "C" void kernel_launch(void* const* d_in, const int* in_sizes, int n_in,
                              void* d_out, int out_size) {
    const float* x  = (const float*)d_in[0];
    const float* Wq = (const float*)d_in[1];
    const float* bq = (const float*)d_in[2];
    const float* Wk = (const float*)d_in[3];
    const float* bk = (const float*)d_in[4];
    const float* Wv = (const float*)d_in[5];
    const float* bv = (const float*)d_in[6];
    float* out = (float*)d_out;
    (void)in_sizes; (void)n_in; (void)out_size;

    cudaFuncSetAttribute(stageA, cudaFuncAttributeMaxDynamicSharedMemorySize, SA_SMEM);
    cudaFuncSetAttribute(stageB, cudaFuncAttributeMaxDynamicSharedMemorySize, SB_SMEM);

    zero_kv_kernel<<<256, 256>>>();
    stageA<<<GRIDA, 256, SA_SMEM>>>(x, Wk, bk, Wv, bv);
    stageB<<<GRIDB, 256, SB_SMEM>>>(x, Wq, bq, out);
}